// round 9
// baseline (speedup 1.0000x reference)
#include <cuda_runtime.h>
#include <cuda_bf16.h>
#include <cuda_fp16.h>
#include <cstdint>

// Problem constants
#define NB 2
#define NT 2048
#define NC 1024
#define NH 16
#define ND 64
#define NP 16
#define NS 2064      // NP + NT
#define SPAD 2112    // 33 chunks of 64
#define NROWS 4096   // NB * NT

// ---------------------------------------------------------------------------
// Scratch (allocation-free: __device__ globals). Packed-pair u32 arrays.
// ---------------------------------------------------------------------------
__device__ uint32_t g_xh[(size_t)NROWS*NC/2];        // x split hi, [row][512] bf16x2
__device__ uint32_t g_xl[(size_t)NROWS*NC/2];
__device__ uint32_t g_ath[(size_t)NROWS*NC/2];       // attention out split hi
__device__ uint32_t g_atl[(size_t)NROWS*NC/2];
__device__ uint32_t g_qh[NB*NH*NT*ND/2];             // bf16x2 [bh][t][d/2] (q*0.125)
__device__ uint32_t g_ql[NB*NH*NT*ND/2];
__device__ uint32_t g_kh[NB*NH*SPAD*ND/2];           // bf16x2 [bh][s][d/2]
__device__ uint32_t g_kl[NB*NH*SPAD*ND/2];
__device__ uint32_t g_vh[NB*NH*SPAD*ND/2];           // fp16x2
// Pre-transposed + hi/lo-split weights, [N][K=1024] bf16
__device__ unsigned short g_wqkv_h[3*NC*NC];
__device__ unsigned short g_wqkv_l[3*NC*NC];
__device__ unsigned short g_wout_h[NC*NC];
__device__ unsigned short g_wout_l[NC*NC];

// ---------------------------------------------------------------------------
// Helpers (family-agnostic: ldmatrix / mma.sync / cp.async only)
// ---------------------------------------------------------------------------
__device__ __forceinline__ uint32_t smem_u32(const void* p) {
    uint32_t a;
    asm("{ .reg .u64 t; cvta.to.shared.u64 t, %1; cvt.u32.u64 %0, t; }" : "=r"(a) : "l"(p));
    return a;
}

#define CP_ASYNC16(dst, src) \
    asm volatile("cp.async.cg.shared.global [%0], [%1], 16;" :: "r"(dst), "l"(src) : "memory")
#define CP_COMMIT() asm volatile("cp.async.commit_group;" ::: "memory")
#define CP_WAIT0()  asm volatile("cp.async.wait_group 0;" ::: "memory")
#define CP_WAIT1()  asm volatile("cp.async.wait_group 1;" ::: "memory")

#define SW128(o) ((o) ^ (((o) >> 3) & 0x70))
__device__ __forceinline__ uint32_t swz(uint32_t base, uint32_t off) {
    return base + SW128(off);
}

__device__ __forceinline__ void ldsm_x4(uint32_t& r0, uint32_t& r1, uint32_t& r2, uint32_t& r3,
                                        uint32_t addr) {
    asm volatile("ldmatrix.sync.aligned.m8n8.x4.shared.b16 {%0,%1,%2,%3}, [%4];"
                 : "=r"(r0), "=r"(r1), "=r"(r2), "=r"(r3) : "r"(addr));
}
__device__ __forceinline__ void ldsm_x4t(uint32_t& r0, uint32_t& r1, uint32_t& r2, uint32_t& r3,
                                         uint32_t addr) {
    asm volatile("ldmatrix.sync.aligned.m8n8.x4.trans.shared.b16 {%0,%1,%2,%3}, [%4];"
                 : "=r"(r0), "=r"(r1), "=r"(r2), "=r"(r3) : "r"(addr));
}

__device__ __forceinline__ void mma_bf16(float* d, const uint32_t* a, const uint32_t* b) {
    asm volatile("mma.sync.aligned.m16n8k16.row.col.f32.bf16.bf16.f32 "
                 "{%0,%1,%2,%3}, {%4,%5,%6,%7}, {%8,%9}, {%0,%1,%2,%3};"
                 : "+f"(d[0]), "+f"(d[1]), "+f"(d[2]), "+f"(d[3])
                 : "r"(a[0]), "r"(a[1]), "r"(a[2]), "r"(a[3]), "r"(b[0]), "r"(b[1]));
}
__device__ __forceinline__ void mma_f16(float* d, const uint32_t* a, const uint32_t* b) {
    asm volatile("mma.sync.aligned.m16n8k16.row.col.f32.f16.f16.f32 "
                 "{%0,%1,%2,%3}, {%4,%5,%6,%7}, {%8,%9}, {%0,%1,%2,%3};"
                 : "+f"(d[0]), "+f"(d[1]), "+f"(d[2]), "+f"(d[3])
                 : "r"(a[0]), "r"(a[1]), "r"(a[2]), "r"(a[3]), "r"(b[0]), "r"(b[1]));
}

// hi/lo bf16 split of two floats packed into two u32
__device__ __forceinline__ void cvt2(float a, float b, uint32_t& h, uint32_t& l) {
    __nv_bfloat16 ha = __float2bfloat16_rn(a);
    __nv_bfloat16 hb = __float2bfloat16_rn(b);
    __nv_bfloat16 la = __float2bfloat16_rn(a - __bfloat162float(ha));
    __nv_bfloat16 lb = __float2bfloat16_rn(b - __bfloat162float(hb));
    h = ((uint32_t)__bfloat16_as_ushort(hb) << 16) | (uint32_t)__bfloat16_as_ushort(ha);
    l = ((uint32_t)__bfloat16_as_ushort(lb) << 16) | (uint32_t)__bfloat16_as_ushort(la);
}
__device__ __forceinline__ uint32_t h2pack(float a, float b) {
    __half2 h = __floats2half2_rn(a, b);
    return *reinterpret_cast<uint32_t*>(&h);
}

// ---------------------------------------------------------------------------
// x prep: fp32 [4096][1024] -> bf16 hi/lo packed pairs [4096][512]
// ---------------------------------------------------------------------------
__global__ void xprep_kernel(const float* __restrict__ x) {
    int idx = blockIdx.x * blockDim.x + threadIdx.x;   // pair index
    if (idx >= NROWS * (NC/2)) return;
    float2 v = *(const float2*)(x + 2 * (size_t)idx);
    uint32_t h, l;
    cvt2(v.x, v.y, h, l);
    g_xh[idx] = h;
    g_xl[idx] = l;
}

// ---------------------------------------------------------------------------
// Weight prep: W [K=1024][N] fp32 -> Wt_h/Wt_l [N][1024] bf16 (hi/lo split)
// ---------------------------------------------------------------------------
__global__ void wprep_kernel(const float* __restrict__ W, int N,
                             unsigned short* __restrict__ Wt_h,
                             unsigned short* __restrict__ Wt_l) {
    __shared__ float tile[32][33];
    const int n0 = blockIdx.x * 32, k0 = blockIdx.y * 32;
    const int tx = threadIdx.x, ty = threadIdx.y;  // 32 x 8
#pragma unroll
    for (int i = 0; i < 32; i += 8)
        tile[ty + i][tx] = W[(size_t)(k0 + ty + i) * N + n0 + tx];
    __syncthreads();
#pragma unroll
    for (int i = 0; i < 32; i += 8) {
        float v = tile[tx][ty + i];
        __nv_bfloat16 h = __float2bfloat16_rn(v);
        __nv_bfloat16 l = __float2bfloat16_rn(v - __bfloat162float(h));
        size_t o = (size_t)(n0 + ty + i) * NC + k0 + tx;
        Wt_h[o] = __bfloat16_as_ushort(h);
        Wt_l[o] = __bfloat16_as_ushort(l);
    }
}

// ---------------------------------------------------------------------------
// Prefix fill + K/V pad rows
// ---------------------------------------------------------------------------
__global__ void prefix_fill_kernel(const float* __restrict__ pk,
                                   const float* __restrict__ pv) {
    int idx = blockIdx.x * blockDim.x + threadIdx.x;
    if (idx < NH*NP*32) {
        int h = idx >> 9;
        int p = (idx >> 5) & (NP - 1);
        int dp = idx & 31;
        const float* kp = pk + ((size_t)h * NP + p) * ND + 2*dp;
        const float* vp = pv + ((size_t)h * NP + p) * ND + 2*dp;
        uint32_t kh, kl;
        cvt2(kp[0], kp[1], kh, kl);
        uint32_t vh = h2pack(vp[0], vp[1]);
#pragma unroll
        for (int b = 0; b < NB; b++) {
            size_t o = ((size_t)(b*NH + h) * SPAD + p) * 32 + dp;
            g_kh[o] = kh; g_kl[o] = kl; g_vh[o] = vh;
        }
    } else {
        int j = idx - NH*NP*32;
        if (j < NB*NH*48*32) {
            int bh = j / (48*32);
            int rem = j % (48*32);
            int r = NS + (rem >> 5);
            int dp = rem & 31;
            size_t o = ((size_t)bh * SPAD + r) * 32 + dp;
            g_kh[o] = 0; g_kl[o] = 0; g_vh[o] = 0;
        }
    }
}

// ---------------------------------------------------------------------------
// mma.sync GEMM, 512 threads = 16 warps (4m x 4n), warp tile 32x32.
// C[M,N] = A @ Wt^T, 3-term split (AhBh + AlBh + AhBl), pre-split operands.
// CTA 128x128 tile, K chunks of 64, double-buffered smem (128KB).
// Per k16 step: 4+4 ldsm, then 3 passes of 8 independent MMAs.
// MODE 0: epilogue scatters split q (x0.125) / k (bf16) / v (fp16).
// MODE 1: epilogue adds bias, writes fp32 d_out.
// ---------------------------------------------------------------------------
#define GEMM_SMEM (2*65536 + 1024)
#define NCH 16

template<int MODE>
__global__ __launch_bounds__(512) void mma_gemm_kernel(
        const unsigned short* __restrict__ Ah_g,
        const unsigned short* __restrict__ Al_g,
        const unsigned short* __restrict__ Wh,
        const unsigned short* __restrict__ Wl,
        const float* __restrict__ bias,
        float* __restrict__ out) {
    extern __shared__ char dsm[];
    const uint32_t sb = (smem_u32(dsm) + 1023u) & ~1023u;

    const int tid = threadIdx.x;
    const int lane = tid & 31;
    const int wid = tid >> 5;
    const int wm = wid & 3;                 // warp m index (0..3), rows 32*wm
    const int wn = wid >> 2;                // warp n index (0..3), cols 32*wn
    const int r0 = blockIdx.y * 128;
    const int c0 = blockIdx.x * 128;

    const uint32_t a_off = (uint32_t)((32*wm + (lane & 15)) * 128 + (lane >> 4) * 16);
    const uint32_t b_off = (uint32_t)((32*wn + ((lane >> 4) & 1) * 8 + (lane & 7)) * 128
                                      + ((lane >> 3) & 1) * 16);
    const int ldrow = tid >> 3;             // 0..63
    const int ldc8  = (tid & 7) * 8;

    float acc[2][4][4];
#pragma unroll
    for (int mf = 0; mf < 2; mf++)
#pragma unroll
        for (int ng = 0; ng < 4; ng++)
#pragma unroll
            for (int c = 0; c < 4; c++) acc[mf][ng][c] = 0.f;

    auto loadStage = [&](int ch, uint32_t bb) {
#pragma unroll
        for (int it = 0; it < 2; ++it) {
            int row = ldrow + it * 64;
            uint32_t off = SW128((uint32_t)(row * 128 + ldc8 * 2));
            size_t ga = (size_t)(r0 + row) * NC + ch * 64 + ldc8;
            CP_ASYNC16(bb + off,           Ah_g + ga);
            CP_ASYNC16(bb + 16384u + off,  Al_g + ga);
            size_t gb = (size_t)(c0 + row) * NC + ch * 64 + ldc8;
            CP_ASYNC16(bb + 32768u + off,  Wh + gb);
            CP_ASYNC16(bb + 49152u + off,  Wl + gb);
        }
    };

    loadStage(0, sb);
    CP_COMMIT();

    for (int ch = 0; ch < NCH; ++ch) {
        const uint32_t base  = sb + (uint32_t)(ch & 1) * 65536u;
        const uint32_t nbase = sb + (uint32_t)((ch & 1) ^ 1) * 65536u;
        if (ch + 1 < NCH) {
            loadStage(ch + 1, nbase);
            CP_COMMIT();
            CP_WAIT1();
        } else {
            CP_WAIT0();
        }
        __syncthreads();   // stage ch visible to all

        const uint32_t bAh = base, bAl = base + 16384u;
        const uint32_t bBh = base + 32768u, bBl = base + 49152u;
#pragma unroll
        for (int kk = 0; kk < 4; ++kk) {
            uint32_t Ahf[2][4], Alf[2][4];
#pragma unroll
            for (int mf = 0; mf < 2; mf++) {
                uint32_t o = a_off + kk * 32 + mf * 2048;
                ldsm_x4(Ahf[mf][0], Ahf[mf][1], Ahf[mf][2], Ahf[mf][3], swz(bAh, o));
                ldsm_x4(Alf[mf][0], Alf[mf][1], Alf[mf][2], Alf[mf][3], swz(bAl, o));
            }
            uint32_t Bhf[2][4], Blf[2][4];
#pragma unroll
            for (int j = 0; j < 2; ++j) {   // j covers n8 groups 2j, 2j+1
                uint32_t o = b_off + j * 2048 + kk * 32;
                ldsm_x4(Bhf[j][0], Bhf[j][1], Bhf[j][2], Bhf[j][3], swz(bBh, o));
                ldsm_x4(Blf[j][0], Blf[j][1], Blf[j][2], Blf[j][3], swz(bBl, o));
            }
            // pass 1: Ah x Bh — 8 independent MMAs
#pragma unroll
            for (int j = 0; j < 2; ++j)
#pragma unroll
                for (int mf = 0; mf < 2; mf++) {
                    mma_bf16(acc[mf][2*j],   Ahf[mf], Bhf[j]);
                    mma_bf16(acc[mf][2*j+1], Ahf[mf], Bhf[j] + 2);
                }
            // pass 2: Al x Bh
#pragma unroll
            for (int j = 0; j < 2; ++j)
#pragma unroll
                for (int mf = 0; mf < 2; mf++) {
                    mma_bf16(acc[mf][2*j],   Alf[mf], Bhf[j]);
                    mma_bf16(acc[mf][2*j+1], Alf[mf], Bhf[j] + 2);
                }
            // pass 3: Ah x Bl
#pragma unroll
            for (int j = 0; j < 2; ++j)
#pragma unroll
                for (int mf = 0; mf < 2; mf++) {
                    mma_bf16(acc[mf][2*j],   Ahf[mf], Blf[j]);
                    mma_bf16(acc[mf][2*j+1], Ahf[mf], Blf[j] + 2);
                }
        }
        __syncthreads();   // all reads of 'base' done before ch+2 overwrites
    }

    // ---- epilogue ----
    const int g4 = lane >> 2, t4 = lane & 3;
    const int colb = c0 + 32 * wn;
    const int which = colb >> 10;               // MODE 0 only
    const int hh = (colb >> 6) & (NH - 1);
#pragma unroll
    for (int ng = 0; ng < 4; ++ng) {
        const int col = colb + 8 * ng + 2 * t4;
        const float b0v = bias[col], b1v = bias[col + 1];
#pragma unroll
        for (int mf = 0; mf < 2; mf++) {
            const int row = r0 + 32 * wm + 16 * mf + g4;
            const float* ac = acc[mf][ng];
            if (MODE == 1) {
                float2 v0 = make_float2(ac[0] + b0v, ac[1] + b1v);
                float2 v1 = make_float2(ac[2] + b0v, ac[3] + b1v);
                *(float2*)&out[(size_t)row * NC + col] = v0;
                *(float2*)&out[(size_t)(row + 8) * NC + col] = v1;
            } else {
                const int dp = (col & (ND - 1)) >> 1;   // d-pair index 0..31
#pragma unroll
                for (int rr = 0; rr < 2; rr++) {
                    const int r = row + 8*rr;
                    const int b = r >> 11, t = r & (NT - 1);
                    const int bh = b * NH + hh;
                    float x = ac[2*rr] + b0v, y = ac[2*rr+1] + b1v;
                    if (which == 0) {
                        uint32_t h, l;
                        cvt2(x * 0.125f, y * 0.125f, h, l);
                        size_t o = ((size_t)bh * NT + t) * 32 + dp;
                        g_qh[o] = h; g_ql[o] = l;
                    } else if (which == 1) {
                        uint32_t h, l;
                        cvt2(x, y, h, l);
                        size_t o = ((size_t)bh * SPAD + NP + t) * 32 + dp;
                        g_kh[o] = h; g_kl[o] = l;
                    } else {
                        size_t o = ((size_t)bh * SPAD + NP + t) * 32 + dp;
                        g_vh[o] = h2pack(x, y);
                    }
                }
            }
        }
    }
}

// ---------------------------------------------------------------------------
// Tensor-core flash attention (unchanged from passing R8 kernel).
// ---------------------------------------------------------------------------
#define ATTN_SMEM (16384*2 + 2*24576 + 1024)
#define NCHUNK 33

__global__ __launch_bounds__(256, 2) void attn_kernel() {
    extern __shared__ char dsm[];
    const uint32_t sb  = (smem_u32(dsm) + 1023u) & ~1023u;
    const uint32_t sQh = sb, sQl = sb + 16384u;
    const uint32_t sBuf0 = sb + 32768u;       // each buf: Kh | Kl | V (8K each)

    const int bh = blockIdx.y;
    const int q0 = blockIdx.x * 128;
    const int b = bh >> 4, h = bh & (NH - 1);
    const int tid = threadIdx.x;
    const int lane = tid & 31;
    const int wid = tid >> 5;

    const uint32_t* Qhp = g_qh + ((size_t)bh * NT + q0) * 32;
    const uint32_t* Qlp = g_ql + ((size_t)bh * NT + q0) * 32;
    const uint32_t* Khp = g_kh + (size_t)bh * SPAD * 32;
    const uint32_t* Klp = g_kl + (size_t)bh * SPAD * 32;
    const uint32_t* Vhp = g_vh + (size_t)bh * SPAD * 32;

    const uint32_t a_off = (uint32_t)((16*wid + (lane & 15)) * 128 + (lane >> 4) * 16);
    const uint32_t b_off = (uint32_t)((((lane >> 4) & 1) * 8 + (lane & 7)) * 128
                                      + ((lane >> 3) & 1) * 16);
    const uint32_t v_off = (uint32_t)((lane & 15) * 128 + (lane >> 4) * 16);

#pragma unroll
    for (int it = 0; it < 8; ++it) {
        int idx = tid + it * 256;
        int ten = idx >> 10;
        int r = (idx & 1023) >> 3;
        int seg = idx & 7;
        const uint32_t* src = (ten ? Qlp : Qhp) + (size_t)r * 32 + seg * 4;
        uint32_t dst = (ten ? sQl : sQh) + SW128((uint32_t)(r * 128 + seg * 16));
        CP_ASYNC16(dst, src);
    }
    auto loadChunk = [&](int ci, uint32_t bb) {
#pragma unroll
        for (int it = 0; it < 6; ++it) {
            int idx = tid + it * 256;
            int ten = idx / 512;
            int r = (idx & 511) >> 3;
            int seg = idx & 7;
            const uint32_t* base = (ten == 0) ? Khp : (ten == 1) ? Klp : Vhp;
            const uint32_t* src = base + (size_t)(ci * 64 + r) * 32 + seg * 4;
            uint32_t dst = bb + (uint32_t)ten * 8192u + SW128((uint32_t)(r * 128 + seg * 16));
            CP_ASYNC16(dst, src);
        }
    };
    loadChunk(0, sBuf0);
    CP_COMMIT();

    float O[8][4];
#pragma unroll
    for (int g = 0; g < 8; g++)
#pragma unroll
        for (int c = 0; c < 4; c++) O[g][c] = 0.f;
    float m0 = -1e30f, m1 = -1e30f, l0 = 0.f, l1 = 0.f;

    for (int ci = 0; ci < NCHUNK; ++ci) {
        const uint32_t buf  = sBuf0 + (uint32_t)(ci & 1) * 24576u;
        const uint32_t nbuf = sBuf0 + (uint32_t)((ci & 1) ^ 1) * 24576u;
        if (ci + 1 < NCHUNK) {
            loadChunk(ci + 1, nbuf);
            CP_COMMIT();
            CP_WAIT1();
        } else {
            CP_WAIT0();
        }
        __syncthreads();

        const uint32_t bKh = buf, bKl = buf + 8192u, bV = buf + 16384u;

        // ---- S = Q K^T (3-term split), gg processed in pairs for ILP ----
        float S[8][4];
#pragma unroll
        for (int g = 0; g < 8; g++)
#pragma unroll
            for (int c = 0; c < 4; c++) S[g][c] = 0.f;
#pragma unroll
        for (int kk = 0; kk < 4; ++kk) {
            uint32_t Ahf[4], Alf[4];
            ldsm_x4(Ahf[0], Ahf[1], Ahf[2], Ahf[3], swz(sQh, a_off + kk * 32));
            ldsm_x4(Alf[0], Alf[1], Alf[2], Alf[3], swz(sQl, a_off + kk * 32));
#pragma unroll
            for (int gp = 0; gp < 2; ++gp) {
                uint32_t K0h[4], K0l[4], K1h[4], K1l[4];
                uint32_t o0 = b_off + (2*gp) * 2048 + kk * 32;
                uint32_t o1 = b_off + (2*gp+1) * 2048 + kk * 32;
                ldsm_x4(K0h[0], K0h[1], K0h[2], K0h[3], swz(bKh, o0));
                ldsm_x4(K0l[0], K0l[1], K0l[2], K0l[3], swz(bKl, o0));
                ldsm_x4(K1h[0], K1h[1], K1h[2], K1h[3], swz(bKh, o1));
                ldsm_x4(K1l[0], K1l[1], K1l[2], K1l[3], swz(bKl, o1));
                float* s0 = S[4*gp];
                float* s1 = S[4*gp+1];
                float* s2 = S[4*gp+2];
                float* s3 = S[4*gp+3];
                // pass 1: Qh x Kh (4 independent)
                mma_bf16(s0, Ahf, K0h); mma_bf16(s1, Ahf, K0h + 2);
                mma_bf16(s2, Ahf, K1h); mma_bf16(s3, Ahf, K1h + 2);
                // pass 2: Ql x Kh
                mma_bf16(s0, Alf, K0h); mma_bf16(s1, Alf, K0h + 2);
                mma_bf16(s2, Alf, K1h); mma_bf16(s3, Alf, K1h + 2);
                // pass 3: Qh x Kl
                mma_bf16(s0, Ahf, K0l); mma_bf16(s1, Ahf, K0l + 2);
                mma_bf16(s2, Ahf, K1l); mma_bf16(s3, Ahf, K1l + 2);
            }
        }

        // ---- tail mask (chunk 32: only cols 0..15 valid => frags g>=2) ----
        if (ci == NCHUNK - 1) {
#pragma unroll
            for (int g = 2; g < 8; g++)
#pragma unroll
                for (int c = 0; c < 4; c++) S[g][c] = -1e30f;
        }

        // ---- online softmax ----
        float tm0 = -1e30f, tm1 = -1e30f;
#pragma unroll
        for (int g = 0; g < 8; g++) {
            tm0 = fmaxf(tm0, fmaxf(S[g][0], S[g][1]));
            tm1 = fmaxf(tm1, fmaxf(S[g][2], S[g][3]));
        }
        tm0 = fmaxf(tm0, __shfl_xor_sync(0xffffffffu, tm0, 1));
        tm0 = fmaxf(tm0, __shfl_xor_sync(0xffffffffu, tm0, 2));
        tm1 = fmaxf(tm1, __shfl_xor_sync(0xffffffffu, tm1, 1));
        tm1 = fmaxf(tm1, __shfl_xor_sync(0xffffffffu, tm1, 2));
        float mn0 = fmaxf(m0, tm0), mn1 = fmaxf(m1, tm1);
        float al0 = __expf(m0 - mn0), al1 = __expf(m1 - mn1);
        float s0 = 0.f, s1 = 0.f;
#pragma unroll
        for (int g = 0; g < 8; g++) {
            S[g][0] = __expf(S[g][0] - mn0);
            S[g][1] = __expf(S[g][1] - mn0);
            S[g][2] = __expf(S[g][2] - mn1);
            S[g][3] = __expf(S[g][3] - mn1);
            s0 += S[g][0] + S[g][1];
            s1 += S[g][2] + S[g][3];
        }
        s0 += __shfl_xor_sync(0xffffffffu, s0, 1);
        s0 += __shfl_xor_sync(0xffffffffu, s0, 2);
        s1 += __shfl_xor_sync(0xffffffffu, s1, 1);
        s1 += __shfl_xor_sync(0xffffffffu, s1, 2);
        l0 = l0 * al0 + s0; l1 = l1 * al1 + s1;
        m0 = mn0; m1 = mn1;
#pragma unroll
        for (int g = 0; g < 8; g++) {
            O[g][0] *= al0; O[g][1] *= al0;
            O[g][2] *= al1; O[g][3] *= al1;
        }

        // ---- pack P to fp16 A-frags ----
        uint32_t pa[4][4];
#pragma unroll
        for (int kk = 0; kk < 4; ++kk) {
            pa[kk][0] = h2pack(S[2*kk][0],   S[2*kk][1]);
            pa[kk][1] = h2pack(S[2*kk][2],   S[2*kk][3]);
            pa[kk][2] = h2pack(S[2*kk+1][0], S[2*kk+1][1]);
            pa[kk][3] = h2pack(S[2*kk+1][2], S[2*kk+1][3]);
        }

        // ---- O += P V ----
#pragma unroll
        for (int kk = 0; kk < 4; ++kk) {
#pragma unroll
            for (int gg = 0; gg < 4; ++gg) {
                uint32_t Vb[4];
                uint32_t o = v_off + kk * 2048 + gg * 32;
                ldsm_x4t(Vb[0], Vb[1], Vb[2], Vb[3], swz(bV, o));
                mma_f16(O[2*gg],   pa[kk], Vb);
                mma_f16(O[2*gg+1], pa[kk], Vb + 2);
            }
        }
        __syncthreads();
    }

    // ---- epilogue: normalize, split to bf16 hi/lo, write g_ath/g_atl ----
    const float inv0 = 1.f / l0, inv1 = 1.f / l1;
    const int r = lane >> 2;
    const int row0 = q0 + 16*wid + r;
#pragma unroll
    for (int g = 0; g < 8; g++) {
        const int dp = h * 32 + 4*g + (lane & 3);   // pair index within row
        uint32_t hh, ll;
        cvt2(O[g][0] * inv0, O[g][1] * inv0, hh, ll);
        size_t o0 = (size_t)(b*NT + row0) * 512 + dp;
        g_ath[o0] = hh; g_atl[o0] = ll;
        cvt2(O[g][2] * inv1, O[g][3] * inv1, hh, ll);
        size_t o1 = (size_t)(b*NT + row0 + 8) * 512 + dp;
        g_ath[o1] = hh; g_atl[o1] = ll;
    }
}

// ---------------------------------------------------------------------------
// Launch
// ---------------------------------------------------------------------------
extern "C" void kernel_launch(void* const* d_in, const int* in_sizes, int n_in,
                              void* d_out, int out_size) {
    const float* x    = (const float*)d_in[0];
    const float* pk   = (const float*)d_in[1];
    const float* pv   = (const float*)d_in[2];
    const float* Wqkv = (const float*)d_in[3];
    const float* bqkv = (const float*)d_in[4];
    const float* Wout = (const float*)d_in[5];
    const float* bout = (const float*)d_in[6];
    float* out = (float*)d_out;

    cudaFuncSetAttribute(attn_kernel,
                         cudaFuncAttributeMaxDynamicSharedMemorySize, ATTN_SMEM);
    cudaFuncSetAttribute(mma_gemm_kernel<0>,
                         cudaFuncAttributeMaxDynamicSharedMemorySize, GEMM_SMEM);
    cudaFuncSetAttribute(mma_gemm_kernel<1>,
                         cudaFuncAttributeMaxDynamicSharedMemorySize, GEMM_SMEM);

    unsigned short *wqh, *wql, *woh, *wol, *xh, *xl, *ath, *atl;
    cudaGetSymbolAddress((void**)&wqh, g_wqkv_h);
    cudaGetSymbolAddress((void**)&wql, g_wqkv_l);
    cudaGetSymbolAddress((void**)&woh, g_wout_h);
    cudaGetSymbolAddress((void**)&wol, g_wout_l);
    cudaGetSymbolAddress((void**)&xh,  g_xh);
    cudaGetSymbolAddress((void**)&xl,  g_xl);
    cudaGetSymbolAddress((void**)&ath, g_ath);
    cudaGetSymbolAddress((void**)&atl, g_atl);

    dim3 tb(32, 8);
    wprep_kernel<<<dim3(96, 32), tb>>>(Wqkv, 3*NC, wqh, wql);
    wprep_kernel<<<dim3(32, 32), tb>>>(Wout,   NC, woh, wol);
    prefix_fill_kernel<<<224, 256>>>(pk, pv);
    xprep_kernel<<<NROWS*(NC/2)/256, 256>>>(x);

    mma_gemm_kernel<0><<<dim3(24, 32), 512, GEMM_SMEM>>>(xh, xl, wqh, wql, bqkv, nullptr);
    attn_kernel<<<dim3(16, 32), 256, ATTN_SMEM>>>();
    mma_gemm_kernel<1><<<dim3(8, 32), 512, GEMM_SMEM>>>(ath, atl, woh, wol, bout, out);
}

// round 10
// speedup vs baseline: 1.4097x; 1.4097x over previous
#include <cuda_runtime.h>
#include <cuda_bf16.h>
#include <cuda_fp16.h>
#include <cstdint>

// Problem constants
#define NB 2
#define NT 2048
#define NC 1024
#define NH 16
#define ND 64
#define NP 16
#define NS 2064      // NP + NT
#define SPAD 2112    // 33 chunks of 64
#define NROWS 4096   // NB * NT

// ---------------------------------------------------------------------------
// Scratch (allocation-free: __device__ globals). Packed-pair u32 arrays.
// All fp16x2 now.
// ---------------------------------------------------------------------------
__device__ uint32_t g_xh[(size_t)NROWS*NC/2];        // x fp16-hi pairs [row][512]
__device__ uint32_t g_xl[(size_t)NROWS*NC/2];        // fp16-lo residual
__device__ uint32_t g_ath[(size_t)NROWS*NC/2];       // attention out fp16 hi
__device__ uint32_t g_atl[(size_t)NROWS*NC/2];
__device__ uint32_t g_qh[NB*NH*NT*ND/2];             // q fp16-hi (x0.125)
__device__ uint32_t g_ql[NB*NH*NT*ND/2];             // q fp16-lo
__device__ uint32_t g_kh[NB*NH*SPAD*ND/2];           // k fp16 (single)
__device__ uint32_t g_vh[NB*NH*SPAD*ND/2];           // v fp16
// Pre-transposed fp16 weights, [N][K=1024]
__device__ __half g_wqkv[3*NC*NC];
__device__ __half g_wout[NC*NC];

// ---------------------------------------------------------------------------
// Helpers (family-agnostic: ldmatrix / mma.sync / cp.async only)
// ---------------------------------------------------------------------------
__device__ __forceinline__ uint32_t smem_u32(const void* p) {
    uint32_t a;
    asm("{ .reg .u64 t; cvta.to.shared.u64 t, %1; cvt.u32.u64 %0, t; }" : "=r"(a) : "l"(p));
    return a;
}

#define CP_ASYNC16(dst, src) \
    asm volatile("cp.async.cg.shared.global [%0], [%1], 16;" :: "r"(dst), "l"(src) : "memory")
#define CP_COMMIT() asm volatile("cp.async.commit_group;" ::: "memory")
#define CP_WAIT0()  asm volatile("cp.async.wait_group 0;" ::: "memory")
#define CP_WAIT1()  asm volatile("cp.async.wait_group 1;" ::: "memory")

#define SW128(o) ((o) ^ (((o) >> 3) & 0x70))
__device__ __forceinline__ uint32_t swz(uint32_t base, uint32_t off) {
    return base + SW128(off);
}

__device__ __forceinline__ void ldsm_x4(uint32_t& r0, uint32_t& r1, uint32_t& r2, uint32_t& r3,
                                        uint32_t addr) {
    asm volatile("ldmatrix.sync.aligned.m8n8.x4.shared.b16 {%0,%1,%2,%3}, [%4];"
                 : "=r"(r0), "=r"(r1), "=r"(r2), "=r"(r3) : "r"(addr));
}
__device__ __forceinline__ void ldsm_x4t(uint32_t& r0, uint32_t& r1, uint32_t& r2, uint32_t& r3,
                                         uint32_t addr) {
    asm volatile("ldmatrix.sync.aligned.m8n8.x4.trans.shared.b16 {%0,%1,%2,%3}, [%4];"
                 : "=r"(r0), "=r"(r1), "=r"(r2), "=r"(r3) : "r"(addr));
}

__device__ __forceinline__ void mma_f16(float* d, const uint32_t* a, const uint32_t* b) {
    asm volatile("mma.sync.aligned.m16n8k16.row.col.f32.f16.f16.f32 "
                 "{%0,%1,%2,%3}, {%4,%5,%6,%7}, {%8,%9}, {%0,%1,%2,%3};"
                 : "+f"(d[0]), "+f"(d[1]), "+f"(d[2]), "+f"(d[3])
                 : "r"(a[0]), "r"(a[1]), "r"(a[2]), "r"(a[3]), "r"(b[0]), "r"(b[1]));
}

// hi/lo fp16 split of two floats packed into two u32 (~22-bit combined)
__device__ __forceinline__ void cvt2h(float a, float b, uint32_t& h, uint32_t& l) {
    __half ha = __float2half_rn(a);
    __half hb = __float2half_rn(b);
    __half la = __float2half_rn(a - __half2float(ha));
    __half lb = __float2half_rn(b - __half2float(hb));
    h = ((uint32_t)__half_as_ushort(hb) << 16) | (uint32_t)__half_as_ushort(ha);
    l = ((uint32_t)__half_as_ushort(lb) << 16) | (uint32_t)__half_as_ushort(la);
}
__device__ __forceinline__ uint32_t h2pack(float a, float b) {
    __half2 h = __floats2half2_rn(a, b);
    return *reinterpret_cast<uint32_t*>(&h);
}

// ---------------------------------------------------------------------------
// x prep: fp32 [4096][1024] -> fp16 hi/lo packed pairs [4096][512]
// ---------------------------------------------------------------------------
__global__ void xprep_kernel(const float* __restrict__ x) {
    int idx = blockIdx.x * blockDim.x + threadIdx.x;   // pair index
    if (idx >= NROWS * (NC/2)) return;
    float2 v = *(const float2*)(x + 2 * (size_t)idx);
    uint32_t h, l;
    cvt2h(v.x, v.y, h, l);
    g_xh[idx] = h;
    g_xl[idx] = l;
}

// ---------------------------------------------------------------------------
// Weight prep: W [K=1024][N] fp32 -> Wt [N][1024] fp16
// ---------------------------------------------------------------------------
__global__ void wprep_kernel(const float* __restrict__ W, int N,
                             __half* __restrict__ Wt) {
    __shared__ float tile[32][33];
    const int n0 = blockIdx.x * 32, k0 = blockIdx.y * 32;
    const int tx = threadIdx.x, ty = threadIdx.y;  // 32 x 8
#pragma unroll
    for (int i = 0; i < 32; i += 8)
        tile[ty + i][tx] = W[(size_t)(k0 + ty + i) * N + n0 + tx];
    __syncthreads();
#pragma unroll
    for (int i = 0; i < 32; i += 8) {
        float v = tile[tx][ty + i];
        Wt[(size_t)(n0 + ty + i) * NC + k0 + tx] = __float2half_rn(v);
    }
}

// ---------------------------------------------------------------------------
// Prefix fill + K/V pad rows (fp16)
// ---------------------------------------------------------------------------
__global__ void prefix_fill_kernel(const float* __restrict__ pk,
                                   const float* __restrict__ pv) {
    int idx = blockIdx.x * blockDim.x + threadIdx.x;
    if (idx < NH*NP*32) {
        int h = idx >> 9;
        int p = (idx >> 5) & (NP - 1);
        int dp = idx & 31;
        const float* kp = pk + ((size_t)h * NP + p) * ND + 2*dp;
        const float* vp = pv + ((size_t)h * NP + p) * ND + 2*dp;
        uint32_t kh = h2pack(kp[0], kp[1]);
        uint32_t vh = h2pack(vp[0], vp[1]);
#pragma unroll
        for (int b = 0; b < NB; b++) {
            size_t o = ((size_t)(b*NH + h) * SPAD + p) * 32 + dp;
            g_kh[o] = kh; g_vh[o] = vh;
        }
    } else {
        int j = idx - NH*NP*32;
        if (j < NB*NH*48*32) {
            int bh = j / (48*32);
            int rem = j % (48*32);
            int r = NS + (rem >> 5);
            int dp = rem & 31;
            size_t o = ((size_t)bh * SPAD + r) * 32 + dp;
            g_kh[o] = 0; g_vh[o] = 0;
        }
    }
}

// ---------------------------------------------------------------------------
// mma.sync GEMM, fp16 2-pass split: C = (Ah+Al) @ B^T, A 2-term fp16, B fp16.
// CTA 128x128, 256 threads = 8 warps (4m x 2n), warp tile 32x64.
// K chunks of 64, double-buffered smem: (Ah 16K | Al 16K | B 16K) x2 = 96KB.
// 2 CTAs/SM (launch_bounds(256,2), regs<=128).
// MODE 0: epilogue scatters q hi/lo (x0.125) / k fp16 / v fp16.
// MODE 1: epilogue adds bias, writes fp32 d_out.
// ---------------------------------------------------------------------------
#define GEMM_SMEM (2*49152 + 1024)
#define NCH 16

template<int MODE>
__global__ __launch_bounds__(256, 2) void mma_gemm_kernel(
        const uint32_t* __restrict__ Ah_g,
        const uint32_t* __restrict__ Al_g,
        const __half* __restrict__ W,
        const float* __restrict__ bias,
        float* __restrict__ out) {
    extern __shared__ char dsm[];
    const uint32_t sb = (smem_u32(dsm) + 1023u) & ~1023u;

    const int tid = threadIdx.x;
    const int lane = tid & 31;
    const int wm = (tid >> 5) & 3;          // warp m (0..3), rows 32*wm
    const int wn = tid >> 7;                // warp n (0..1), cols 64*wn
    const int r0 = blockIdx.y * 128;
    const int c0 = blockIdx.x * 128;

    const uint32_t a_off = (uint32_t)((32*wm + (lane & 15)) * 128 + (lane >> 4) * 16);
    const uint32_t b_off = (uint32_t)((64*wn + ((lane >> 4) & 1) * 8 + (lane & 7)) * 128
                                      + ((lane >> 3) & 1) * 16);
    const int ldrow = tid >> 3;             // 0..31
    const int ldc8  = (tid & 7) * 8;        // fp16-element col offset

    float acc[2][8][4];
#pragma unroll
    for (int mf = 0; mf < 2; mf++)
#pragma unroll
        for (int ng = 0; ng < 8; ng++)
#pragma unroll
            for (int c = 0; c < 4; c++) acc[mf][ng][c] = 0.f;

    auto loadStage = [&](int ch, uint32_t bb) {
#pragma unroll
        for (int it = 0; it < 4; ++it) {
            int row = ldrow + it * 32;
            uint32_t off = SW128((uint32_t)(row * 128 + ldc8 * 2));
            size_t ga = (size_t)(r0 + row) * (NC/2) + (ch * 64 + ldc8) / 2;
            CP_ASYNC16(bb + off,          Ah_g + ga);
            CP_ASYNC16(bb + 16384u + off, Al_g + ga);
            size_t gb = (size_t)(c0 + row) * NC + ch * 64 + ldc8;
            CP_ASYNC16(bb + 32768u + off, W + gb);
        }
    };

    loadStage(0, sb);
    CP_COMMIT();

    for (int ch = 0; ch < NCH; ++ch) {
        const uint32_t base  = sb + (uint32_t)(ch & 1) * 49152u;
        const uint32_t nbase = sb + (uint32_t)((ch & 1) ^ 1) * 49152u;
        if (ch + 1 < NCH) {
            loadStage(ch + 1, nbase);
            CP_COMMIT();
            CP_WAIT1();
        } else {
            CP_WAIT0();
        }
        __syncthreads();

        const uint32_t bAh = base, bAl = base + 16384u, bB = base + 32768u;
#pragma unroll
        for (int kk = 0; kk < 4; ++kk) {
            uint32_t Ahf[2][4], Alf[2][4];
#pragma unroll
            for (int mf = 0; mf < 2; mf++) {
                uint32_t o = a_off + kk * 32 + mf * 2048;
                ldsm_x4(Ahf[mf][0], Ahf[mf][1], Ahf[mf][2], Ahf[mf][3], swz(bAh, o));
                ldsm_x4(Alf[mf][0], Alf[mf][1], Alf[mf][2], Alf[mf][3], swz(bAl, o));
            }
            uint32_t Bf[4][4];
#pragma unroll
            for (int g = 0; g < 4; ++g) {
                uint32_t o = b_off + g * 2048 + kk * 32;
                ldsm_x4(Bf[g][0], Bf[g][1], Bf[g][2], Bf[g][3], swz(bB, o));
            }
            // pass 1: Ah x B — 16 independent MMAs
#pragma unroll
            for (int g = 0; g < 4; ++g)
#pragma unroll
                for (int mf = 0; mf < 2; mf++) {
                    mma_f16(acc[mf][2*g],   Ahf[mf], Bf[g]);
                    mma_f16(acc[mf][2*g+1], Ahf[mf], Bf[g] + 2);
                }
            // pass 2: Al x B
#pragma unroll
            for (int g = 0; g < 4; ++g)
#pragma unroll
                for (int mf = 0; mf < 2; mf++) {
                    mma_f16(acc[mf][2*g],   Alf[mf], Bf[g]);
                    mma_f16(acc[mf][2*g+1], Alf[mf], Bf[g] + 2);
                }
        }
        __syncthreads();
    }

    // ---- epilogue ----
    const int g4 = lane >> 2, t4 = lane & 3;
    const int colb = c0 + 64 * wn;
    const int which = colb >> 10;               // MODE 0 only
    const int hh = (colb >> 6) & (NH - 1);
#pragma unroll
    for (int ng = 0; ng < 8; ++ng) {
        const int col = colb + 8 * ng + 2 * t4;
        const float b0v = bias[col], b1v = bias[col + 1];
#pragma unroll
        for (int mf = 0; mf < 2; mf++) {
            const int row = r0 + 32 * wm + 16 * mf + g4;
            const float* ac = acc[mf][ng];
            if (MODE == 1) {
                float2 v0 = make_float2(ac[0] + b0v, ac[1] + b1v);
                float2 v1 = make_float2(ac[2] + b0v, ac[3] + b1v);
                *(float2*)&out[(size_t)row * NC + col] = v0;
                *(float2*)&out[(size_t)(row + 8) * NC + col] = v1;
            } else {
                const int dp = (col & (ND - 1)) >> 1;
#pragma unroll
                for (int rr = 0; rr < 2; rr++) {
                    const int r = row + 8*rr;
                    const int b = r >> 11, t = r & (NT - 1);
                    const int bh = b * NH + hh;
                    float x = ac[2*rr] + b0v, y = ac[2*rr+1] + b1v;
                    if (which == 0) {
                        uint32_t h, l;
                        cvt2h(x * 0.125f, y * 0.125f, h, l);
                        size_t o = ((size_t)bh * NT + t) * 32 + dp;
                        g_qh[o] = h; g_ql[o] = l;
                    } else if (which == 1) {
                        size_t o = ((size_t)bh * SPAD + NP + t) * 32 + dp;
                        g_kh[o] = h2pack(x, y);
                    } else {
                        size_t o = ((size_t)bh * SPAD + NP + t) * 32 + dp;
                        g_vh[o] = h2pack(x, y);
                    }
                }
            }
        }
    }
}

// ---------------------------------------------------------------------------
// Tensor-core flash attention, fp16 2-pass QK (Qh*K + Ql*K), fp16 PV.
// smem: Qh 16K | Ql 16K | 2 x (K 8K | V 8K) = 64K (+pad).
// ---------------------------------------------------------------------------
#define ATTN_SMEM (16384*2 + 2*16384 + 1024)
#define NCHUNK 33

__global__ __launch_bounds__(256, 2) void attn_kernel() {
    extern __shared__ char dsm[];
    const uint32_t sb  = (smem_u32(dsm) + 1023u) & ~1023u;
    const uint32_t sQh = sb, sQl = sb + 16384u;
    const uint32_t sBuf0 = sb + 32768u;       // each buf: K 8K | V 8K

    const int bh = blockIdx.y;
    const int q0 = blockIdx.x * 128;
    const int b = bh >> 4, h = bh & (NH - 1);
    const int tid = threadIdx.x;
    const int lane = tid & 31;
    const int wid = tid >> 5;

    const uint32_t* Qhp = g_qh + ((size_t)bh * NT + q0) * 32;
    const uint32_t* Qlp = g_ql + ((size_t)bh * NT + q0) * 32;
    const uint32_t* Khp = g_kh + (size_t)bh * SPAD * 32;
    const uint32_t* Vhp = g_vh + (size_t)bh * SPAD * 32;

    const uint32_t a_off = (uint32_t)((16*wid + (lane & 15)) * 128 + (lane >> 4) * 16);
    const uint32_t b_off = (uint32_t)((((lane >> 4) & 1) * 8 + (lane & 7)) * 128
                                      + ((lane >> 3) & 1) * 16);
    const uint32_t v_off = (uint32_t)((lane & 15) * 128 + (lane >> 4) * 16);

#pragma unroll
    for (int it = 0; it < 8; ++it) {
        int idx = tid + it * 256;
        int ten = idx >> 10;
        int r = (idx & 1023) >> 3;
        int seg = idx & 7;
        const uint32_t* src = (ten ? Qlp : Qhp) + (size_t)r * 32 + seg * 4;
        uint32_t dst = (ten ? sQl : sQh) + SW128((uint32_t)(r * 128 + seg * 16));
        CP_ASYNC16(dst, src);
    }
    auto loadChunk = [&](int ci, uint32_t bb) {
#pragma unroll
        for (int it = 0; it < 4; ++it) {
            int idx = tid + it * 256;           // 0..1023
            int ten = idx >> 9;                 // 0 K, 1 V
            int r = (idx & 511) >> 3;
            int seg = idx & 7;
            const uint32_t* base = ten ? Vhp : Khp;
            const uint32_t* src = base + (size_t)(ci * 64 + r) * 32 + seg * 4;
            uint32_t dst = bb + (uint32_t)ten * 8192u + SW128((uint32_t)(r * 128 + seg * 16));
            CP_ASYNC16(dst, src);
        }
    };
    loadChunk(0, sBuf0);
    CP_COMMIT();

    float O[8][4];
#pragma unroll
    for (int g = 0; g < 8; g++)
#pragma unroll
        for (int c = 0; c < 4; c++) O[g][c] = 0.f;
    float m0 = -1e30f, m1 = -1e30f, l0 = 0.f, l1 = 0.f;

    for (int ci = 0; ci < NCHUNK; ++ci) {
        const uint32_t buf  = sBuf0 + (uint32_t)(ci & 1) * 16384u;
        const uint32_t nbuf = sBuf0 + (uint32_t)((ci & 1) ^ 1) * 16384u;
        if (ci + 1 < NCHUNK) {
            loadChunk(ci + 1, nbuf);
            CP_COMMIT();
            CP_WAIT1();
        } else {
            CP_WAIT0();
        }
        __syncthreads();

        const uint32_t bK = buf, bV = buf + 8192u;

        // ---- S = Q K^T (2-pass fp16 split) ----
        float S[8][4];
#pragma unroll
        for (int g = 0; g < 8; g++)
#pragma unroll
            for (int c = 0; c < 4; c++) S[g][c] = 0.f;
#pragma unroll
        for (int kk = 0; kk < 4; ++kk) {
            uint32_t Ahf[4], Alf[4];
            ldsm_x4(Ahf[0], Ahf[1], Ahf[2], Ahf[3], swz(sQh, a_off + kk * 32));
            ldsm_x4(Alf[0], Alf[1], Alf[2], Alf[3], swz(sQl, a_off + kk * 32));
#pragma unroll
            for (int gp = 0; gp < 2; ++gp) {
                uint32_t K0[4], K1[4];
                uint32_t o0 = b_off + (2*gp) * 2048 + kk * 32;
                uint32_t o1 = b_off + (2*gp+1) * 2048 + kk * 32;
                ldsm_x4(K0[0], K0[1], K0[2], K0[3], swz(bK, o0));
                ldsm_x4(K1[0], K1[1], K1[2], K1[3], swz(bK, o1));
                float* s0 = S[4*gp];
                float* s1 = S[4*gp+1];
                float* s2 = S[4*gp+2];
                float* s3 = S[4*gp+3];
                // pass 1: Qh x K (4 independent)
                mma_f16(s0, Ahf, K0); mma_f16(s1, Ahf, K0 + 2);
                mma_f16(s2, Ahf, K1); mma_f16(s3, Ahf, K1 + 2);
                // pass 2: Ql x K
                mma_f16(s0, Alf, K0); mma_f16(s1, Alf, K0 + 2);
                mma_f16(s2, Alf, K1); mma_f16(s3, Alf, K1 + 2);
            }
        }

        // ---- tail mask (chunk 32: only cols 0..15 valid => frags g>=2) ----
        if (ci == NCHUNK - 1) {
#pragma unroll
            for (int g = 2; g < 8; g++)
#pragma unroll
                for (int c = 0; c < 4; c++) S[g][c] = -1e30f;
        }

        // ---- online softmax ----
        float tm0 = -1e30f, tm1 = -1e30f;
#pragma unroll
        for (int g = 0; g < 8; g++) {
            tm0 = fmaxf(tm0, fmaxf(S[g][0], S[g][1]));
            tm1 = fmaxf(tm1, fmaxf(S[g][2], S[g][3]));
        }
        tm0 = fmaxf(tm0, __shfl_xor_sync(0xffffffffu, tm0, 1));
        tm0 = fmaxf(tm0, __shfl_xor_sync(0xffffffffu, tm0, 2));
        tm1 = fmaxf(tm1, __shfl_xor_sync(0xffffffffu, tm1, 1));
        tm1 = fmaxf(tm1, __shfl_xor_sync(0xffffffffu, tm1, 2));
        float mn0 = fmaxf(m0, tm0), mn1 = fmaxf(m1, tm1);
        float al0 = __expf(m0 - mn0), al1 = __expf(m1 - mn1);
        float s0 = 0.f, s1 = 0.f;
#pragma unroll
        for (int g = 0; g < 8; g++) {
            S[g][0] = __expf(S[g][0] - mn0);
            S[g][1] = __expf(S[g][1] - mn0);
            S[g][2] = __expf(S[g][2] - mn1);
            S[g][3] = __expf(S[g][3] - mn1);
            s0 += S[g][0] + S[g][1];
            s1 += S[g][2] + S[g][3];
        }
        s0 += __shfl_xor_sync(0xffffffffu, s0, 1);
        s0 += __shfl_xor_sync(0xffffffffu, s0, 2);
        s1 += __shfl_xor_sync(0xffffffffu, s1, 1);
        s1 += __shfl_xor_sync(0xffffffffu, s1, 2);
        l0 = l0 * al0 + s0; l1 = l1 * al1 + s1;
        m0 = mn0; m1 = mn1;
#pragma unroll
        for (int g = 0; g < 8; g++) {
            O[g][0] *= al0; O[g][1] *= al0;
            O[g][2] *= al1; O[g][3] *= al1;
        }

        // ---- pack P to fp16 A-frags ----
        uint32_t pa[4][4];
#pragma unroll
        for (int kk = 0; kk < 4; ++kk) {
            pa[kk][0] = h2pack(S[2*kk][0],   S[2*kk][1]);
            pa[kk][1] = h2pack(S[2*kk][2],   S[2*kk][3]);
            pa[kk][2] = h2pack(S[2*kk+1][0], S[2*kk+1][1]);
            pa[kk][3] = h2pack(S[2*kk+1][2], S[2*kk+1][3]);
        }

        // ---- O += P V ----
#pragma unroll
        for (int kk = 0; kk < 4; ++kk) {
#pragma unroll
            for (int gg = 0; gg < 4; ++gg) {
                uint32_t Vb[4];
                uint32_t o = v_off + kk * 2048 + gg * 32;
                ldsm_x4t(Vb[0], Vb[1], Vb[2], Vb[3], swz(bV, o));
                mma_f16(O[2*gg],   pa[kk], Vb);
                mma_f16(O[2*gg+1], pa[kk], Vb + 2);
            }
        }
        __syncthreads();
    }

    // ---- epilogue: normalize, fp16 hi/lo split, write g_ath/g_atl ----
    const float inv0 = 1.f / l0, inv1 = 1.f / l1;
    const int r = lane >> 2;
    const int row0 = q0 + 16*wid + r;
#pragma unroll
    for (int g = 0; g < 8; g++) {
        const int dp = h * 32 + 4*g + (lane & 3);   // pair index within row
        uint32_t hh, ll;
        cvt2h(O[g][0] * inv0, O[g][1] * inv0, hh, ll);
        size_t o0 = (size_t)(b*NT + row0) * 512 + dp;
        g_ath[o0] = hh; g_atl[o0] = ll;
        cvt2h(O[g][2] * inv1, O[g][3] * inv1, hh, ll);
        size_t o1 = (size_t)(b*NT + row0 + 8) * 512 + dp;
        g_ath[o1] = hh; g_atl[o1] = ll;
    }
}

// ---------------------------------------------------------------------------
// Launch
// ---------------------------------------------------------------------------
extern "C" void kernel_launch(void* const* d_in, const int* in_sizes, int n_in,
                              void* d_out, int out_size) {
    const float* x    = (const float*)d_in[0];
    const float* pk   = (const float*)d_in[1];
    const float* pv   = (const float*)d_in[2];
    const float* Wqkv = (const float*)d_in[3];
    const float* bqkv = (const float*)d_in[4];
    const float* Wout = (const float*)d_in[5];
    const float* bout = (const float*)d_in[6];
    float* out = (float*)d_out;

    cudaFuncSetAttribute(attn_kernel,
                         cudaFuncAttributeMaxDynamicSharedMemorySize, ATTN_SMEM);
    cudaFuncSetAttribute(mma_gemm_kernel<0>,
                         cudaFuncAttributeMaxDynamicSharedMemorySize, GEMM_SMEM);
    cudaFuncSetAttribute(mma_gemm_kernel<1>,
                         cudaFuncAttributeMaxDynamicSharedMemorySize, GEMM_SMEM);

    __half *wq, *wo;
    uint32_t *xh, *xl, *ath, *atl;
    cudaGetSymbolAddress((void**)&wq,  g_wqkv);
    cudaGetSymbolAddress((void**)&wo,  g_wout);
    cudaGetSymbolAddress((void**)&xh,  g_xh);
    cudaGetSymbolAddress((void**)&xl,  g_xl);
    cudaGetSymbolAddress((void**)&ath, g_ath);
    cudaGetSymbolAddress((void**)&atl, g_atl);

    dim3 tb(32, 8);
    wprep_kernel<<<dim3(96, 32), tb>>>(Wqkv, 3*NC, wq);
    wprep_kernel<<<dim3(32, 32), tb>>>(Wout,   NC, wo);
    prefix_fill_kernel<<<224, 256>>>(pk, pv);
    xprep_kernel<<<NROWS*(NC/2)/256, 256>>>(x);

    mma_gemm_kernel<0><<<dim3(24, 32), 256, GEMM_SMEM>>>(xh, xl, wq, bqkv, nullptr);
    attn_kernel<<<dim3(16, 32), 256, ATTN_SMEM>>>();
    mma_gemm_kernel<1><<<dim3(8, 32), 256, GEMM_SMEM>>>(ath, atl, wo, bout, out);
}

// round 12
// speedup vs baseline: 1.5355x; 1.0893x over previous
#include <cuda_runtime.h>
#include <cuda_bf16.h>
#include <cuda_fp16.h>
#include <cstdint>

// Problem constants
#define NB 2
#define NT 2048
#define NC 1024
#define NH 16
#define ND 64
#define NP 16
#define NS 2064      // NP + NT
#define SPAD 2112    // 33 chunks of 64
#define NROWS 4096   // NB * NT

// ---------------------------------------------------------------------------
// Scratch (allocation-free: __device__ globals). Packed-pair u32 arrays.
// ---------------------------------------------------------------------------
__device__ uint32_t g_xh[(size_t)NROWS*NC/2];        // x fp16-hi pairs [row][512]
__device__ uint32_t g_xl[(size_t)NROWS*NC/2];        // fp16-lo residual
__device__ uint32_t g_ath[(size_t)NROWS*NC/2];       // attention out fp16 hi
__device__ uint32_t g_atl[(size_t)NROWS*NC/2];
__device__ uint32_t g_qh[NB*NH*NT*ND/2];             // q fp16 (x0.125), single
__device__ uint32_t g_kh[NB*NH*SPAD*ND/2];           // k fp16 (single)
__device__ uint32_t g_vh[NB*NH*SPAD*ND/2];           // v fp16
// Pre-transposed fp16 weights, [N][K=1024]
__device__ __half g_wqkv[3*NC*NC];
__device__ __half g_wout[NC*NC];

// ---------------------------------------------------------------------------
// Helpers (family-agnostic: ldmatrix / mma.sync / cp.async only)
// ---------------------------------------------------------------------------
__device__ __forceinline__ uint32_t smem_u32(const void* p) {
    uint32_t a;
    asm("{ .reg .u64 t; cvta.to.shared.u64 t, %1; cvt.u32.u64 %0, t; }" : "=r"(a) : "l"(p));
    return a;
}

#define CP_ASYNC16(dst, src) \
    asm volatile("cp.async.cg.shared.global [%0], [%1], 16;" :: "r"(dst), "l"(src) : "memory")
#define CP_COMMIT() asm volatile("cp.async.commit_group;" ::: "memory")
#define CP_WAIT0()  asm volatile("cp.async.wait_group 0;" ::: "memory")
#define CP_WAIT1()  asm volatile("cp.async.wait_group 1;" ::: "memory")

#define SW128(o) ((o) ^ (((o) >> 3) & 0x70))
__device__ __forceinline__ uint32_t swz(uint32_t base, uint32_t off) {
    return base + SW128(off);
}

__device__ __forceinline__ void ldsm_x4(uint32_t& r0, uint32_t& r1, uint32_t& r2, uint32_t& r3,
                                        uint32_t addr) {
    asm volatile("ldmatrix.sync.aligned.m8n8.x4.shared.b16 {%0,%1,%2,%3}, [%4];"
                 : "=r"(r0), "=r"(r1), "=r"(r2), "=r"(r3) : "r"(addr));
}
__device__ __forceinline__ void ldsm_x4t(uint32_t& r0, uint32_t& r1, uint32_t& r2, uint32_t& r3,
                                         uint32_t addr) {
    asm volatile("ldmatrix.sync.aligned.m8n8.x4.trans.shared.b16 {%0,%1,%2,%3}, [%4];"
                 : "=r"(r0), "=r"(r1), "=r"(r2), "=r"(r3) : "r"(addr));
}

__device__ __forceinline__ void mma_f16(float* d, const uint32_t* a, const uint32_t* b) {
    asm volatile("mma.sync.aligned.m16n8k16.row.col.f32.f16.f16.f32 "
                 "{%0,%1,%2,%3}, {%4,%5,%6,%7}, {%8,%9}, {%0,%1,%2,%3};"
                 : "+f"(d[0]), "+f"(d[1]), "+f"(d[2]), "+f"(d[3])
                 : "r"(a[0]), "r"(a[1]), "r"(a[2]), "r"(a[3]), "r"(b[0]), "r"(b[1]));
}

// hi/lo fp16 split of two floats packed into two u32 (~22-bit combined)
__device__ __forceinline__ void cvt2h(float a, float b, uint32_t& h, uint32_t& l) {
    __half ha = __float2half_rn(a);
    __half hb = __float2half_rn(b);
    __half la = __float2half_rn(a - __half2float(ha));
    __half lb = __float2half_rn(b - __half2float(hb));
    h = ((uint32_t)__half_as_ushort(hb) << 16) | (uint32_t)__half_as_ushort(ha);
    l = ((uint32_t)__half_as_ushort(lb) << 16) | (uint32_t)__half_as_ushort(la);
}
__device__ __forceinline__ uint32_t h2pack(float a, float b) {
    __half2 h = __floats2half2_rn(a, b);
    return *reinterpret_cast<uint32_t*>(&h);
}

// ---------------------------------------------------------------------------
// x prep: fp32 [4096][1024] -> fp16 hi/lo packed pairs [4096][512]
// ---------------------------------------------------------------------------
__global__ void xprep_kernel(const float* __restrict__ x) {
    int idx = blockIdx.x * blockDim.x + threadIdx.x;   // pair index
    if (idx >= NROWS * (NC/2)) return;
    float2 v = *(const float2*)(x + 2 * (size_t)idx);
    uint32_t h, l;
    cvt2h(v.x, v.y, h, l);
    g_xh[idx] = h;
    g_xl[idx] = l;
}

// ---------------------------------------------------------------------------
// Weight prep: W [K=1024][N] fp32 -> Wt [N][1024] fp16
// ---------------------------------------------------------------------------
__global__ void wprep_kernel(const float* __restrict__ W, int N,
                             __half* __restrict__ Wt) {
    __shared__ float tile[32][33];
    const int n0 = blockIdx.x * 32, k0 = blockIdx.y * 32;
    const int tx = threadIdx.x, ty = threadIdx.y;  // 32 x 8
#pragma unroll
    for (int i = 0; i < 32; i += 8)
        tile[ty + i][tx] = W[(size_t)(k0 + ty + i) * N + n0 + tx];
    __syncthreads();
#pragma unroll
    for (int i = 0; i < 32; i += 8) {
        float v = tile[tx][ty + i];
        Wt[(size_t)(n0 + ty + i) * NC + k0 + tx] = __float2half_rn(v);
    }
}

// ---------------------------------------------------------------------------
// Prefix fill + K/V pad rows (fp16)
// ---------------------------------------------------------------------------
__global__ void prefix_fill_kernel(const float* __restrict__ pk,
                                   const float* __restrict__ pv) {
    int idx = blockIdx.x * blockDim.x + threadIdx.x;
    if (idx < NH*NP*32) {
        int h = idx >> 9;
        int p = (idx >> 5) & (NP - 1);
        int dp = idx & 31;
        const float* kp = pk + ((size_t)h * NP + p) * ND + 2*dp;
        const float* vp = pv + ((size_t)h * NP + p) * ND + 2*dp;
        uint32_t kh = h2pack(kp[0], kp[1]);
        uint32_t vh = h2pack(vp[0], vp[1]);
#pragma unroll
        for (int b = 0; b < NB; b++) {
            size_t o = ((size_t)(b*NH + h) * SPAD + p) * 32 + dp;
            g_kh[o] = kh; g_vh[o] = vh;
        }
    } else {
        int j = idx - NH*NP*32;
        if (j < NB*NH*48*32) {
            int bh = j / (48*32);
            int rem = j % (48*32);
            int r = NS + (rem >> 5);
            int dp = rem & 31;
            size_t o = ((size_t)bh * SPAD + r) * 32 + dp;
            g_kh[o] = 0; g_vh[o] = 0;
        }
    }
}

// ---------------------------------------------------------------------------
// mma.sync GEMM, fp16 2-pass split: C = (Ah+Al) @ B^T, A 2-term fp16, B fp16.
// CTA 128x128, 256 threads = 8 warps (4m x 2n), warp tile 32x64.
// K chunks of 64, double-buffered smem: (Ah 16K | Al 16K | B 16K) x2 = 96KB.
// 2 CTAs/SM.
// MODE 0: epilogue scatters q fp16 (x0.125) / k fp16 / v fp16.
// MODE 1: epilogue adds bias, writes fp32 d_out.
// ---------------------------------------------------------------------------
#define GEMM_SMEM (2*49152 + 1024)
#define NCH 16

template<int MODE>
__global__ __launch_bounds__(256, 2) void mma_gemm_kernel(
        const uint32_t* __restrict__ Ah_g,
        const uint32_t* __restrict__ Al_g,
        const __half* __restrict__ W,
        const float* __restrict__ bias,
        float* __restrict__ out) {
    extern __shared__ char dsm[];
    const uint32_t sb = (smem_u32(dsm) + 1023u) & ~1023u;

    const int tid = threadIdx.x;
    const int lane = tid & 31;
    const int wm = (tid >> 5) & 3;          // warp m (0..3), rows 32*wm
    const int wn = tid >> 7;                // warp n (0..1), cols 64*wn
    const int r0 = blockIdx.y * 128;
    const int c0 = blockIdx.x * 128;

    const uint32_t a_off = (uint32_t)((32*wm + (lane & 15)) * 128 + (lane >> 4) * 16);
    const uint32_t b_off = (uint32_t)((64*wn + ((lane >> 4) & 1) * 8 + (lane & 7)) * 128
                                      + ((lane >> 3) & 1) * 16);
    const int ldrow = tid >> 3;             // 0..31
    const int ldc8  = (tid & 7) * 8;        // fp16-element col offset

    float acc[2][8][4];
#pragma unroll
    for (int mf = 0; mf < 2; mf++)
#pragma unroll
        for (int ng = 0; ng < 8; ng++)
#pragma unroll
            for (int c = 0; c < 4; c++) acc[mf][ng][c] = 0.f;

    auto loadStage = [&](int ch, uint32_t bb) {
#pragma unroll
        for (int it = 0; it < 4; ++it) {
            int row = ldrow + it * 32;
            uint32_t off = SW128((uint32_t)(row * 128 + ldc8 * 2));
            size_t ga = (size_t)(r0 + row) * (NC/2) + (ch * 64 + ldc8) / 2;
            CP_ASYNC16(bb + off,          Ah_g + ga);
            CP_ASYNC16(bb + 16384u + off, Al_g + ga);
            size_t gb = (size_t)(c0 + row) * NC + ch * 64 + ldc8;
            CP_ASYNC16(bb + 32768u + off, W + gb);
        }
    };

    loadStage(0, sb);
    CP_COMMIT();

    for (int ch = 0; ch < NCH; ++ch) {
        const uint32_t base  = sb + (uint32_t)(ch & 1) * 49152u;
        const uint32_t nbase = sb + (uint32_t)((ch & 1) ^ 1) * 49152u;
        if (ch + 1 < NCH) {
            loadStage(ch + 1, nbase);
            CP_COMMIT();
            CP_WAIT1();
        } else {
            CP_WAIT0();
        }
        __syncthreads();

        const uint32_t bAh = base, bAl = base + 16384u, bB = base + 32768u;
#pragma unroll
        for (int kk = 0; kk < 4; ++kk) {
            uint32_t Ahf[2][4], Alf[2][4];
#pragma unroll
            for (int mf = 0; mf < 2; mf++) {
                uint32_t o = a_off + kk * 32 + mf * 2048;
                ldsm_x4(Ahf[mf][0], Ahf[mf][1], Ahf[mf][2], Ahf[mf][3], swz(bAh, o));
                ldsm_x4(Alf[mf][0], Alf[mf][1], Alf[mf][2], Alf[mf][3], swz(bAl, o));
            }
            uint32_t Bf[4][4];
#pragma unroll
            for (int g = 0; g < 4; ++g) {
                uint32_t o = b_off + g * 2048 + kk * 32;
                ldsm_x4(Bf[g][0], Bf[g][1], Bf[g][2], Bf[g][3], swz(bB, o));
            }
            // pass 1: Ah x B — 16 independent MMAs
#pragma unroll
            for (int g = 0; g < 4; ++g)
#pragma unroll
                for (int mf = 0; mf < 2; mf++) {
                    mma_f16(acc[mf][2*g],   Ahf[mf], Bf[g]);
                    mma_f16(acc[mf][2*g+1], Ahf[mf], Bf[g] + 2);
                }
            // pass 2: Al x B
#pragma unroll
            for (int g = 0; g < 4; ++g)
#pragma unroll
                for (int mf = 0; mf < 2; mf++) {
                    mma_f16(acc[mf][2*g],   Alf[mf], Bf[g]);
                    mma_f16(acc[mf][2*g+1], Alf[mf], Bf[g] + 2);
                }
        }
        __syncthreads();
    }

    // ---- epilogue ----
    const int g4 = lane >> 2, t4 = lane & 3;
    const int colb = c0 + 64 * wn;
    const int which = colb >> 10;               // MODE 0 only
    const int hh = (colb >> 6) & (NH - 1);
#pragma unroll
    for (int ng = 0; ng < 8; ++ng) {
        const int col = colb + 8 * ng + 2 * t4;
        const float b0v = bias[col], b1v = bias[col + 1];
#pragma unroll
        for (int mf = 0; mf < 2; mf++) {
            const int row = r0 + 32 * wm + 16 * mf + g4;
            const float* ac = acc[mf][ng];
            if (MODE == 1) {
                float2 v0 = make_float2(ac[0] + b0v, ac[1] + b1v);
                float2 v1 = make_float2(ac[2] + b0v, ac[3] + b1v);
                *(float2*)&out[(size_t)row * NC + col] = v0;
                *(float2*)&out[(size_t)(row + 8) * NC + col] = v1;
            } else {
                const int dp = (col & (ND - 1)) >> 1;
#pragma unroll
                for (int rr = 0; rr < 2; rr++) {
                    const int r = row + 8*rr;
                    const int b = r >> 11, t = r & (NT - 1);
                    const int bh = b * NH + hh;
                    float x = ac[2*rr] + b0v, y = ac[2*rr+1] + b1v;
                    if (which == 0) {
                        size_t o = ((size_t)bh * NT + t) * 32 + dp;
                        g_qh[o] = h2pack(x * 0.125f, y * 0.125f);
                    } else if (which == 1) {
                        size_t o = ((size_t)bh * SPAD + NP + t) * 32 + dp;
                        g_kh[o] = h2pack(x, y);
                    } else {
                        size_t o = ((size_t)bh * SPAD + NP + t) * 32 + dp;
                        g_vh[o] = h2pack(x, y);
                    }
                }
            }
        }
    }
}

// ---------------------------------------------------------------------------
// Tensor-core flash attention, single-pass fp16 QK, fp16 PV.
// smem: Q 16K | 2 x (K 8K | V 8K) = 48K (+pad).
// ---------------------------------------------------------------------------
#define ATTN_SMEM (16384 + 2*16384 + 1024)
#define NCHUNK 33

__global__ __launch_bounds__(256, 2) void attn_kernel() {
    extern __shared__ char dsm[];
    const uint32_t sb  = (smem_u32(dsm) + 1023u) & ~1023u;
    const uint32_t sQ = sb;
    const uint32_t sBuf0 = sb + 16384u;       // each buf: K 8K | V 8K

    const int bh = blockIdx.y;
    const int q0 = blockIdx.x * 128;
    const int b = bh >> 4, h = bh & (NH - 1);
    const int tid = threadIdx.x;
    const int lane = tid & 31;
    const int wid = tid >> 5;

    const uint32_t* Qp  = g_qh + ((size_t)bh * NT + q0) * 32;
    const uint32_t* Khp = g_kh + (size_t)bh * SPAD * 32;
    const uint32_t* Vhp = g_vh + (size_t)bh * SPAD * 32;

    const uint32_t a_off = (uint32_t)((16*wid + (lane & 15)) * 128 + (lane >> 4) * 16);
    const uint32_t b_off = (uint32_t)((((lane >> 4) & 1) * 8 + (lane & 7)) * 128
                                      + ((lane >> 3) & 1) * 16);
    const uint32_t v_off = (uint32_t)((lane & 15) * 128 + (lane >> 4) * 16);

    // Q load (once): 128 rows x 128B = 1024 x 16B chunks
#pragma unroll
    for (int it = 0; it < 4; ++it) {
        int idx = tid + it * 256;
        int r = idx >> 3;
        int seg = idx & 7;
        const uint32_t* src = Qp + (size_t)r * 32 + seg * 4;
        uint32_t dst = sQ + SW128((uint32_t)(r * 128 + seg * 16));
        CP_ASYNC16(dst, src);
    }
    auto loadChunk = [&](int ci, uint32_t bb) {
#pragma unroll
        for (int it = 0; it < 4; ++it) {
            int idx = tid + it * 256;           // 0..1023
            int ten = idx >> 9;                 // 0 K, 1 V
            int r = (idx & 511) >> 3;
            int seg = idx & 7;
            const uint32_t* base = ten ? Vhp : Khp;
            const uint32_t* src = base + (size_t)(ci * 64 + r) * 32 + seg * 4;
            uint32_t dst = bb + (uint32_t)ten * 8192u + SW128((uint32_t)(r * 128 + seg * 16));
            CP_ASYNC16(dst, src);
        }
    };
    loadChunk(0, sBuf0);
    CP_COMMIT();

    float O[8][4];
#pragma unroll
    for (int g = 0; g < 8; g++)
#pragma unroll
        for (int c = 0; c < 4; c++) O[g][c] = 0.f;
    float m0 = -1e30f, m1 = -1e30f, l0 = 0.f, l1 = 0.f;

    for (int ci = 0; ci < NCHUNK; ++ci) {
        const uint32_t buf  = sBuf0 + (uint32_t)(ci & 1) * 16384u;
        const uint32_t nbuf = sBuf0 + (uint32_t)((ci & 1) ^ 1) * 16384u;
        if (ci + 1 < NCHUNK) {
            loadChunk(ci + 1, nbuf);
            CP_COMMIT();
            CP_WAIT1();
        } else {
            CP_WAIT0();
        }
        __syncthreads();

        const uint32_t bK = buf, bV = buf + 8192u;

        // ---- S = Q K^T (single-pass fp16) ----
        float S[8][4];
#pragma unroll
        for (int g = 0; g < 8; g++)
#pragma unroll
            for (int c = 0; c < 4; c++) S[g][c] = 0.f;
#pragma unroll
        for (int kk = 0; kk < 4; ++kk) {
            uint32_t Af[4];
            ldsm_x4(Af[0], Af[1], Af[2], Af[3], swz(sQ, a_off + kk * 32));
#pragma unroll
            for (int gp = 0; gp < 2; ++gp) {
                uint32_t K0[4], K1[4];
                uint32_t o0 = b_off + (2*gp) * 2048 + kk * 32;
                uint32_t o1 = b_off + (2*gp+1) * 2048 + kk * 32;
                ldsm_x4(K0[0], K0[1], K0[2], K0[3], swz(bK, o0));
                ldsm_x4(K1[0], K1[1], K1[2], K1[3], swz(bK, o1));
                mma_f16(S[4*gp],   Af, K0); mma_f16(S[4*gp+1], Af, K0 + 2);
                mma_f16(S[4*gp+2], Af, K1); mma_f16(S[4*gp+3], Af, K1 + 2);
            }
        }

        // ---- tail mask (chunk 32: only cols 0..15 valid => frags g>=2) ----
        if (ci == NCHUNK - 1) {
#pragma unroll
            for (int g = 2; g < 8; g++)
#pragma unroll
                for (int c = 0; c < 4; c++) S[g][c] = -1e30f;
        }

        // ---- online softmax ----
        float tm0 = -1e30f, tm1 = -1e30f;
#pragma unroll
        for (int g = 0; g < 8; g++) {
            tm0 = fmaxf(tm0, fmaxf(S[g][0], S[g][1]));
            tm1 = fmaxf(tm1, fmaxf(S[g][2], S[g][3]));
        }
        tm0 = fmaxf(tm0, __shfl_xor_sync(0xffffffffu, tm0, 1));
        tm0 = fmaxf(tm0, __shfl_xor_sync(0xffffffffu, tm0, 2));
        tm1 = fmaxf(tm1, __shfl_xor_sync(0xffffffffu, tm1, 1));
        tm1 = fmaxf(tm1, __shfl_xor_sync(0xffffffffu, tm1, 2));
        float mn0 = fmaxf(m0, tm0), mn1 = fmaxf(m1, tm1);
        float al0 = __expf(m0 - mn0), al1 = __expf(m1 - mn1);
        float s0 = 0.f, s1 = 0.f;
#pragma unroll
        for (int g = 0; g < 8; g++) {
            S[g][0] = __expf(S[g][0] - mn0);
            S[g][1] = __expf(S[g][1] - mn0);
            S[g][2] = __expf(S[g][2] - mn1);
            S[g][3] = __expf(S[g][3] - mn1);
            s0 += S[g][0] + S[g][1];
            s1 += S[g][2] + S[g][3];
        }
        s0 += __shfl_xor_sync(0xffffffffu, s0, 1);
        s0 += __shfl_xor_sync(0xffffffffu, s0, 2);
        s1 += __shfl_xor_sync(0xffffffffu, s1, 1);
        s1 += __shfl_xor_sync(0xffffffffu, s1, 2);
        l0 = l0 * al0 + s0; l1 = l1 * al1 + s1;
        m0 = mn0; m1 = mn1;
#pragma unroll
        for (int g = 0; g < 8; g++) {
            O[g][0] *= al0; O[g][1] *= al0;
            O[g][2] *= al1; O[g][3] *= al1;
        }

        // ---- pack P to fp16 A-frags ----
        uint32_t pa[4][4];
#pragma unroll
        for (int kk = 0; kk < 4; ++kk) {
            pa[kk][0] = h2pack(S[2*kk][0],   S[2*kk][1]);
            pa[kk][1] = h2pack(S[2*kk][2],   S[2*kk][3]);
            pa[kk][2] = h2pack(S[2*kk+1][0], S[2*kk+1][1]);
            pa[kk][3] = h2pack(S[2*kk+1][2], S[2*kk+1][3]);
        }

        // ---- O += P V ----
#pragma unroll
        for (int kk = 0; kk < 4; ++kk) {
#pragma unroll
            for (int gg = 0; gg < 4; ++gg) {
                uint32_t Vb[4];
                uint32_t o = v_off + kk * 2048 + gg * 32;
                ldsm_x4t(Vb[0], Vb[1], Vb[2], Vb[3], swz(bV, o));
                mma_f16(O[2*gg],   pa[kk], Vb);
                mma_f16(O[2*gg+1], pa[kk], Vb + 2);
            }
        }
        __syncthreads();
    }

    // ---- epilogue: normalize, fp16 hi/lo split, write g_ath/g_atl ----
    const float inv0 = 1.f / l0, inv1 = 1.f / l1;
    const int r = lane >> 2;
    const int row0 = q0 + 16*wid + r;
#pragma unroll
    for (int g = 0; g < 8; g++) {
        const int dp = h * 32 + 4*g + (lane & 3);   // pair index within row
        uint32_t hh, ll;
        cvt2h(O[g][0] * inv0, O[g][1] * inv0, hh, ll);
        size_t o0 = (size_t)(b*NT + row0) * 512 + dp;
        g_ath[o0] = hh; g_atl[o0] = ll;
        cvt2h(O[g][2] * inv1, O[g][3] * inv1, hh, ll);
        size_t o1 = (size_t)(b*NT + row0 + 8) * 512 + dp;
        g_ath[o1] = hh; g_atl[o1] = ll;
    }
}

// ---------------------------------------------------------------------------
// Launch
// ---------------------------------------------------------------------------
extern "C" void kernel_launch(void* const* d_in, const int* in_sizes, int n_in,
                              void* d_out, int out_size) {
    const float* x    = (const float*)d_in[0];
    const float* pk   = (const float*)d_in[1];
    const float* pv   = (const float*)d_in[2];
    const float* Wqkv = (const float*)d_in[3];
    const float* bqkv = (const float*)d_in[4];
    const float* Wout = (const float*)d_in[5];
    const float* bout = (const float*)d_in[6];
    float* out = (float*)d_out;

    cudaFuncSetAttribute(attn_kernel,
                         cudaFuncAttributeMaxDynamicSharedMemorySize, ATTN_SMEM);
    cudaFuncSetAttribute(mma_gemm_kernel<0>,
                         cudaFuncAttributeMaxDynamicSharedMemorySize, GEMM_SMEM);
    cudaFuncSetAttribute(mma_gemm_kernel<1>,
                         cudaFuncAttributeMaxDynamicSharedMemorySize, GEMM_SMEM);

    __half *wq, *wo;
    uint32_t *xh, *xl, *ath, *atl;
    cudaGetSymbolAddress((void**)&wq,  g_wqkv);
    cudaGetSymbolAddress((void**)&wo,  g_wout);
    cudaGetSymbolAddress((void**)&xh,  g_xh);
    cudaGetSymbolAddress((void**)&xl,  g_xl);
    cudaGetSymbolAddress((void**)&ath, g_ath);
    cudaGetSymbolAddress((void**)&atl, g_atl);

    dim3 tb(32, 8);
    wprep_kernel<<<dim3(96, 32), tb>>>(Wqkv, 3*NC, wq);
    wprep_kernel<<<dim3(32, 32), tb>>>(Wout,   NC, wo);
    prefix_fill_kernel<<<224, 256>>>(pk, pv);
    xprep_kernel<<<NROWS*(NC/2)/256, 256>>>(x);

    mma_gemm_kernel<0><<<dim3(24, 32), 256, GEMM_SMEM>>>(xh, xl, wq, bqkv, nullptr);
    attn_kernel<<<dim3(16, 32), 256, ATTN_SMEM>>>();
    mma_gemm_kernel<1><<<dim3(8, 32), 256, GEMM_SMEM>>>(ath, atl, wo, bout, out);
}

// round 14
// speedup vs baseline: 1.9927x; 1.2977x over previous
#include <cuda_runtime.h>
#include <cuda_bf16.h>
#include <cuda_fp16.h>
#include <cstdint>

// Problem constants
#define NB 2
#define NT 2048
#define NC 1024
#define NH 16
#define ND 64
#define NP 16
#define NS 2064      // NP + NT
#define SPAD 2112    // 33 chunks of 64
#define NROWS 4096   // NB * NT

// ---------------------------------------------------------------------------
// Scratch (allocation-free: __device__ globals). Packed-pair u32 arrays.
// ---------------------------------------------------------------------------
__device__ uint32_t g_xh[(size_t)NROWS*NC/2];        // x fp16 pairs [row][512]
__device__ uint32_t g_ath[(size_t)NROWS*NC/2];       // attention out fp16 pairs
__device__ uint32_t g_qh[NB*NH*NT*ND/2];             // q fp16 (x0.125)
__device__ uint32_t g_kh[NB*NH*SPAD*ND/2];           // k fp16
__device__ uint32_t g_vh[NB*NH*SPAD*ND/2];           // v fp16
// Pre-transposed fp16 weights, [N][K=1024]
__device__ __half g_wqkv[3*NC*NC];
__device__ __half g_wout[NC*NC];

// ---------------------------------------------------------------------------
// Helpers (family-agnostic: ldmatrix / mma.sync / cp.async only)
// ---------------------------------------------------------------------------
__device__ __forceinline__ uint32_t smem_u32(const void* p) {
    uint32_t a;
    asm("{ .reg .u64 t; cvta.to.shared.u64 t, %1; cvt.u32.u64 %0, t; }" : "=r"(a) : "l"(p));
    return a;
}

#define CP_ASYNC16(dst, src) \
    asm volatile("cp.async.cg.shared.global [%0], [%1], 16;" :: "r"(dst), "l"(src) : "memory")
#define CP_COMMIT() asm volatile("cp.async.commit_group;" ::: "memory")
#define CP_WAIT0()  asm volatile("cp.async.wait_group 0;" ::: "memory")
#define CP_WAIT1()  asm volatile("cp.async.wait_group 1;" ::: "memory")

#define SW128(o) ((o) ^ (((o) >> 3) & 0x70))
__device__ __forceinline__ uint32_t swz(uint32_t base, uint32_t off) {
    return base + SW128(off);
}

__device__ __forceinline__ void ldsm_x4(uint32_t& r0, uint32_t& r1, uint32_t& r2, uint32_t& r3,
                                        uint32_t addr) {
    asm volatile("ldmatrix.sync.aligned.m8n8.x4.shared.b16 {%0,%1,%2,%3}, [%4];"
                 : "=r"(r0), "=r"(r1), "=r"(r2), "=r"(r3) : "r"(addr));
}
__device__ __forceinline__ void ldsm_x4t(uint32_t& r0, uint32_t& r1, uint32_t& r2, uint32_t& r3,
                                         uint32_t addr) {
    asm volatile("ldmatrix.sync.aligned.m8n8.x4.trans.shared.b16 {%0,%1,%2,%3}, [%4];"
                 : "=r"(r0), "=r"(r1), "=r"(r2), "=r"(r3) : "r"(addr));
}

__device__ __forceinline__ void mma_f16(float* d, const uint32_t* a, const uint32_t* b) {
    asm volatile("mma.sync.aligned.m16n8k16.row.col.f32.f16.f16.f32 "
                 "{%0,%1,%2,%3}, {%4,%5,%6,%7}, {%8,%9}, {%0,%1,%2,%3};"
                 : "+f"(d[0]), "+f"(d[1]), "+f"(d[2]), "+f"(d[3])
                 : "r"(a[0]), "r"(a[1]), "r"(a[2]), "r"(a[3]), "r"(b[0]), "r"(b[1]));
}

__device__ __forceinline__ uint32_t h2pack(float a, float b) {
    __half2 h = __floats2half2_rn(a, b);
    return *reinterpret_cast<uint32_t*>(&h);
}

// ---------------------------------------------------------------------------
// x prep: fp32 [4096][1024] -> fp16 packed pairs [4096][512]
// ---------------------------------------------------------------------------
__global__ void xprep_kernel(const float* __restrict__ x) {
    int idx = blockIdx.x * blockDim.x + threadIdx.x;   // pair index
    if (idx >= NROWS * (NC/2)) return;
    float2 v = *(const float2*)(x + 2 * (size_t)idx);
    g_xh[idx] = h2pack(v.x, v.y);
}

// ---------------------------------------------------------------------------
// Weight prep: W [K=1024][N] fp32 -> Wt [N][1024] fp16
// ---------------------------------------------------------------------------
__global__ void wprep_kernel(const float* __restrict__ W, int N,
                             __half* __restrict__ Wt) {
    __shared__ float tile[32][33];
    const int n0 = blockIdx.x * 32, k0 = blockIdx.y * 32;
    const int tx = threadIdx.x, ty = threadIdx.y;  // 32 x 8
#pragma unroll
    for (int i = 0; i < 32; i += 8)
        tile[ty + i][tx] = W[(size_t)(k0 + ty + i) * N + n0 + tx];
    __syncthreads();
#pragma unroll
    for (int i = 0; i < 32; i += 8) {
        float v = tile[tx][ty + i];
        Wt[(size_t)(n0 + ty + i) * NC + k0 + tx] = __float2half_rn(v);
    }
}

// ---------------------------------------------------------------------------
// Prefix fill + K/V pad rows (fp16)
// ---------------------------------------------------------------------------
__global__ void prefix_fill_kernel(const float* __restrict__ pk,
                                   const float* __restrict__ pv) {
    int idx = blockIdx.x * blockDim.x + threadIdx.x;
    if (idx < NH*NP*32) {
        int h = idx >> 9;
        int p = (idx >> 5) & (NP - 1);
        int dp = idx & 31;
        const float* kp = pk + ((size_t)h * NP + p) * ND + 2*dp;
        const float* vp = pv + ((size_t)h * NP + p) * ND + 2*dp;
        uint32_t kh = h2pack(kp[0], kp[1]);
        uint32_t vh = h2pack(vp[0], vp[1]);
#pragma unroll
        for (int b = 0; b < NB; b++) {
            size_t o = ((size_t)(b*NH + h) * SPAD + p) * 32 + dp;
            g_kh[o] = kh; g_vh[o] = vh;
        }
    } else {
        int j = idx - NH*NP*32;
        if (j < NB*NH*48*32) {
            int bh = j / (48*32);
            int rem = j % (48*32);
            int r = NS + (rem >> 5);
            int dp = rem & 31;
            size_t o = ((size_t)bh * SPAD + r) * 32 + dp;
            g_kh[o] = 0; g_vh[o] = 0;
        }
    }
}

// ---------------------------------------------------------------------------
// mma.sync GEMM, single-pass fp16: C = A @ B^T.
// CTA 128x128, 256 threads = 8 warps (4m x 2n), warp tile 32x64.
// K chunks of 64, double-buffered smem: (A 16K | B 16K) x2 = 64KB. 2 CTAs/SM.
// MODE 0: epilogue scatters q fp16 (x0.125) / k fp16 / v fp16.
// MODE 1: epilogue adds bias, writes fp32 d_out.
// ---------------------------------------------------------------------------
#define GEMM_SMEM (2*32768 + 1024)
#define NCH 16

template<int MODE>
__global__ __launch_bounds__(256, 2) void mma_gemm_kernel(
        const uint32_t* __restrict__ A_g,
        const __half* __restrict__ W,
        const float* __restrict__ bias,
        float* __restrict__ out) {
    extern __shared__ char dsm[];
    const uint32_t sb = (smem_u32(dsm) + 1023u) & ~1023u;

    const int tid = threadIdx.x;
    const int lane = tid & 31;
    const int wm = (tid >> 5) & 3;          // warp m (0..3), rows 32*wm
    const int wn = tid >> 7;                // warp n (0..1), cols 64*wn
    const int r0 = blockIdx.y * 128;
    const int c0 = blockIdx.x * 128;

    const uint32_t a_off = (uint32_t)((32*wm + (lane & 15)) * 128 + (lane >> 4) * 16);
    const uint32_t b_off = (uint32_t)((64*wn + ((lane >> 4) & 1) * 8 + (lane & 7)) * 128
                                      + ((lane >> 3) & 1) * 16);
    const int ldrow = tid >> 3;             // 0..31
    const int ldc8  = (tid & 7) * 8;        // fp16-element col offset

    float acc[2][8][4];
#pragma unroll
    for (int mf = 0; mf < 2; mf++)
#pragma unroll
        for (int ng = 0; ng < 8; ng++)
#pragma unroll
            for (int c = 0; c < 4; c++) acc[mf][ng][c] = 0.f;

    auto loadStage = [&](int ch, uint32_t bb) {
#pragma unroll
        for (int it = 0; it < 4; ++it) {
            int row = ldrow + it * 32;
            uint32_t off = SW128((uint32_t)(row * 128 + ldc8 * 2));
            size_t ga = (size_t)(r0 + row) * (NC/2) + (ch * 64 + ldc8) / 2;
            CP_ASYNC16(bb + off, A_g + ga);
            size_t gb = (size_t)(c0 + row) * NC + ch * 64 + ldc8;
            CP_ASYNC16(bb + 16384u + off, W + gb);
        }
    };

    loadStage(0, sb);
    CP_COMMIT();

    for (int ch = 0; ch < NCH; ++ch) {
        const uint32_t base  = sb + (uint32_t)(ch & 1) * 32768u;
        const uint32_t nbase = sb + (uint32_t)((ch & 1) ^ 1) * 32768u;
        if (ch + 1 < NCH) {
            loadStage(ch + 1, nbase);
            CP_COMMIT();
            CP_WAIT1();
        } else {
            CP_WAIT0();
        }
        __syncthreads();

        const uint32_t bA = base, bB = base + 16384u;
#pragma unroll
        for (int kk = 0; kk < 4; ++kk) {
            uint32_t Af[2][4];
#pragma unroll
            for (int mf = 0; mf < 2; mf++) {
                uint32_t o = a_off + kk * 32 + mf * 2048;
                ldsm_x4(Af[mf][0], Af[mf][1], Af[mf][2], Af[mf][3], swz(bA, o));
            }
            uint32_t Bf[4][4];
#pragma unroll
            for (int g = 0; g < 4; ++g) {
                uint32_t o = b_off + g * 2048 + kk * 32;
                ldsm_x4(Bf[g][0], Bf[g][1], Bf[g][2], Bf[g][3], swz(bB, o));
            }
            // 16 independent MMAs
#pragma unroll
            for (int g = 0; g < 4; ++g)
#pragma unroll
                for (int mf = 0; mf < 2; mf++) {
                    mma_f16(acc[mf][2*g],   Af[mf], Bf[g]);
                    mma_f16(acc[mf][2*g+1], Af[mf], Bf[g] + 2);
                }
        }
        __syncthreads();
    }

    // ---- epilogue ----
    const int g4 = lane >> 2, t4 = lane & 3;
    const int colb = c0 + 64 * wn;
    const int which = colb >> 10;               // MODE 0 only
    const int hh = (colb >> 6) & (NH - 1);
#pragma unroll
    for (int ng = 0; ng < 8; ++ng) {
        const int col = colb + 8 * ng + 2 * t4;
        const float b0v = bias[col], b1v = bias[col + 1];
#pragma unroll
        for (int mf = 0; mf < 2; mf++) {
            const int row = r0 + 32 * wm + 16 * mf + g4;
            const float* ac = acc[mf][ng];
            if (MODE == 1) {
                float2 v0 = make_float2(ac[0] + b0v, ac[1] + b1v);
                float2 v1 = make_float2(ac[2] + b0v, ac[3] + b1v);
                *(float2*)&out[(size_t)row * NC + col] = v0;
                *(float2*)&out[(size_t)(row + 8) * NC + col] = v1;
            } else {
                const int dp = (col & (ND - 1)) >> 1;
#pragma unroll
                for (int rr = 0; rr < 2; rr++) {
                    const int r = row + 8*rr;
                    const int b = r >> 11, t = r & (NT - 1);
                    const int bh = b * NH + hh;
                    float x = ac[2*rr] + b0v, y = ac[2*rr+1] + b1v;
                    if (which == 0) {
                        size_t o = ((size_t)bh * NT + t) * 32 + dp;
                        g_qh[o] = h2pack(x * 0.125f, y * 0.125f);
                    } else if (which == 1) {
                        size_t o = ((size_t)bh * SPAD + NP + t) * 32 + dp;
                        g_kh[o] = h2pack(x, y);
                    } else {
                        size_t o = ((size_t)bh * SPAD + NP + t) * 32 + dp;
                        g_vh[o] = h2pack(x, y);
                    }
                }
            }
        }
    }
}

// ---------------------------------------------------------------------------
// Tensor-core flash attention, single-pass fp16 QK, fp16 PV.
// smem: Q 16K | 2 x (K 8K | V 8K) = 48K (+pad).
// ---------------------------------------------------------------------------
#define ATTN_SMEM (16384 + 2*16384 + 1024)
#define NCHUNK 33

__global__ __launch_bounds__(256, 2) void attn_kernel() {
    extern __shared__ char dsm[];
    const uint32_t sb  = (smem_u32(dsm) + 1023u) & ~1023u;
    const uint32_t sQ = sb;
    const uint32_t sBuf0 = sb + 16384u;       // each buf: K 8K | V 8K

    const int bh = blockIdx.y;
    const int q0 = blockIdx.x * 128;
    const int b = bh >> 4, h = bh & (NH - 1);
    const int tid = threadIdx.x;
    const int lane = tid & 31;
    const int wid = tid >> 5;

    const uint32_t* Qp  = g_qh + ((size_t)bh * NT + q0) * 32;
    const uint32_t* Khp = g_kh + (size_t)bh * SPAD * 32;
    const uint32_t* Vhp = g_vh + (size_t)bh * SPAD * 32;

    const uint32_t a_off = (uint32_t)((16*wid + (lane & 15)) * 128 + (lane >> 4) * 16);
    const uint32_t b_off = (uint32_t)((((lane >> 4) & 1) * 8 + (lane & 7)) * 128
                                      + ((lane >> 3) & 1) * 16);
    const uint32_t v_off = (uint32_t)((lane & 15) * 128 + (lane >> 4) * 16);

    // Q load (once): 128 rows x 128B = 1024 x 16B chunks
#pragma unroll
    for (int it = 0; it < 4; ++it) {
        int idx = tid + it * 256;
        int r = idx >> 3;
        int seg = idx & 7;
        const uint32_t* src = Qp + (size_t)r * 32 + seg * 4;
        uint32_t dst = sQ + SW128((uint32_t)(r * 128 + seg * 16));
        CP_ASYNC16(dst, src);
    }
    auto loadChunk = [&](int ci, uint32_t bb) {
#pragma unroll
        for (int it = 0; it < 4; ++it) {
            int idx = tid + it * 256;           // 0..1023
            int ten = idx >> 9;                 // 0 K, 1 V
            int r = (idx & 511) >> 3;
            int seg = idx & 7;
            const uint32_t* base = ten ? Vhp : Khp;
            const uint32_t* src = base + (size_t)(ci * 64 + r) * 32 + seg * 4;
            uint32_t dst = bb + (uint32_t)ten * 8192u + SW128((uint32_t)(r * 128 + seg * 16));
            CP_ASYNC16(dst, src);
        }
    };
    loadChunk(0, sBuf0);
    CP_COMMIT();

    float O[8][4];
#pragma unroll
    for (int g = 0; g < 8; g++)
#pragma unroll
        for (int c = 0; c < 4; c++) O[g][c] = 0.f;
    float m0 = -1e30f, m1 = -1e30f, l0 = 0.f, l1 = 0.f;

    for (int ci = 0; ci < NCHUNK; ++ci) {
        const uint32_t buf  = sBuf0 + (uint32_t)(ci & 1) * 16384u;
        const uint32_t nbuf = sBuf0 + (uint32_t)((ci & 1) ^ 1) * 16384u;
        if (ci + 1 < NCHUNK) {
            loadChunk(ci + 1, nbuf);
            CP_COMMIT();
            CP_WAIT1();
        } else {
            CP_WAIT0();
        }
        __syncthreads();

        const uint32_t bK = buf, bV = buf + 8192u;

        // ---- S = Q K^T (single-pass fp16) ----
        float S[8][4];
#pragma unroll
        for (int g = 0; g < 8; g++)
#pragma unroll
            for (int c = 0; c < 4; c++) S[g][c] = 0.f;
#pragma unroll
        for (int kk = 0; kk < 4; ++kk) {
            uint32_t Af[4];
            ldsm_x4(Af[0], Af[1], Af[2], Af[3], swz(sQ, a_off + kk * 32));
#pragma unroll
            for (int gp = 0; gp < 2; ++gp) {
                uint32_t K0[4], K1[4];
                uint32_t o0 = b_off + (2*gp) * 2048 + kk * 32;
                uint32_t o1 = b_off + (2*gp+1) * 2048 + kk * 32;
                ldsm_x4(K0[0], K0[1], K0[2], K0[3], swz(bK, o0));
                ldsm_x4(K1[0], K1[1], K1[2], K1[3], swz(bK, o1));
                mma_f16(S[4*gp],   Af, K0); mma_f16(S[4*gp+1], Af, K0 + 2);
                mma_f16(S[4*gp+2], Af, K1); mma_f16(S[4*gp+3], Af, K1 + 2);
            }
        }

        // ---- tail mask (chunk 32: only cols 0..15 valid => frags g>=2) ----
        if (ci == NCHUNK - 1) {
#pragma unroll
            for (int g = 2; g < 8; g++)
#pragma unroll
                for (int c = 0; c < 4; c++) S[g][c] = -1e30f;
        }

        // ---- online softmax ----
        float tm0 = -1e30f, tm1 = -1e30f;
#pragma unroll
        for (int g = 0; g < 8; g++) {
            tm0 = fmaxf(tm0, fmaxf(S[g][0], S[g][1]));
            tm1 = fmaxf(tm1, fmaxf(S[g][2], S[g][3]));
        }
        tm0 = fmaxf(tm0, __shfl_xor_sync(0xffffffffu, tm0, 1));
        tm0 = fmaxf(tm0, __shfl_xor_sync(0xffffffffu, tm0, 2));
        tm1 = fmaxf(tm1, __shfl_xor_sync(0xffffffffu, tm1, 1));
        tm1 = fmaxf(tm1, __shfl_xor_sync(0xffffffffu, tm1, 2));
        float mn0 = fmaxf(m0, tm0), mn1 = fmaxf(m1, tm1);
        float al0 = __expf(m0 - mn0), al1 = __expf(m1 - mn1);
        float s0 = 0.f, s1 = 0.f;
#pragma unroll
        for (int g = 0; g < 8; g++) {
            S[g][0] = __expf(S[g][0] - mn0);
            S[g][1] = __expf(S[g][1] - mn0);
            S[g][2] = __expf(S[g][2] - mn1);
            S[g][3] = __expf(S[g][3] - mn1);
            s0 += S[g][0] + S[g][1];
            s1 += S[g][2] + S[g][3];
        }
        s0 += __shfl_xor_sync(0xffffffffu, s0, 1);
        s0 += __shfl_xor_sync(0xffffffffu, s0, 2);
        s1 += __shfl_xor_sync(0xffffffffu, s1, 1);
        s1 += __shfl_xor_sync(0xffffffffu, s1, 2);
        l0 = l0 * al0 + s0; l1 = l1 * al1 + s1;
        m0 = mn0; m1 = mn1;
#pragma unroll
        for (int g = 0; g < 8; g++) {
            O[g][0] *= al0; O[g][1] *= al0;
            O[g][2] *= al1; O[g][3] *= al1;
        }

        // ---- pack P to fp16 A-frags ----
        uint32_t pa[4][4];
#pragma unroll
        for (int kk = 0; kk < 4; ++kk) {
            pa[kk][0] = h2pack(S[2*kk][0],   S[2*kk][1]);
            pa[kk][1] = h2pack(S[2*kk][2],   S[2*kk][3]);
            pa[kk][2] = h2pack(S[2*kk+1][0], S[2*kk+1][1]);
            pa[kk][3] = h2pack(S[2*kk+1][2], S[2*kk+1][3]);
        }

        // ---- O += P V ----
#pragma unroll
        for (int kk = 0; kk < 4; ++kk) {
#pragma unroll
            for (int gg = 0; gg < 4; ++gg) {
                uint32_t Vb[4];
                uint32_t o = v_off + kk * 2048 + gg * 32;
                ldsm_x4t(Vb[0], Vb[1], Vb[2], Vb[3], swz(bV, o));
                mma_f16(O[2*gg],   pa[kk], Vb);
                mma_f16(O[2*gg+1], pa[kk], Vb + 2);
            }
        }
        __syncthreads();
    }

    // ---- epilogue: normalize, pack fp16, write g_ath ----
    const float inv0 = 1.f / l0, inv1 = 1.f / l1;
    const int r = lane >> 2;
    const int row0 = q0 + 16*wid + r;
#pragma unroll
    for (int g = 0; g < 8; g++) {
        const int dp = h * 32 + 4*g + (lane & 3);   // pair index within row
        size_t o0 = (size_t)(b*NT + row0) * 512 + dp;
        g_ath[o0] = h2pack(O[g][0] * inv0, O[g][1] * inv0);
        size_t o1 = (size_t)(b*NT + row0 + 8) * 512 + dp;
        g_ath[o1] = h2pack(O[g][2] * inv1, O[g][3] * inv1);
    }
}

// ---------------------------------------------------------------------------
// Launch
// ---------------------------------------------------------------------------
extern "C" void kernel_launch(void* const* d_in, const int* in_sizes, int n_in,
                              void* d_out, int out_size) {
    const float* x    = (const float*)d_in[0];
    const float* pk   = (const float*)d_in[1];
    const float* pv   = (const float*)d_in[2];
    const float* Wqkv = (const float*)d_in[3];
    const float* bqkv = (const float*)d_in[4];
    const float* Wout = (const float*)d_in[5];
    const float* bout = (const float*)d_in[6];
    float* out = (float*)d_out;

    cudaFuncSetAttribute(attn_kernel,
                         cudaFuncAttributeMaxDynamicSharedMemorySize, ATTN_SMEM);
    cudaFuncSetAttribute(mma_gemm_kernel<0>,
                         cudaFuncAttributeMaxDynamicSharedMemorySize, GEMM_SMEM);
    cudaFuncSetAttribute(mma_gemm_kernel<1>,
                         cudaFuncAttributeMaxDynamicSharedMemorySize, GEMM_SMEM);

    __half *wq, *wo;
    uint32_t *xh, *ath;
    cudaGetSymbolAddress((void**)&wq,  g_wqkv);
    cudaGetSymbolAddress((void**)&wo,  g_wout);
    cudaGetSymbolAddress((void**)&xh,  g_xh);
    cudaGetSymbolAddress((void**)&ath, g_ath);

    dim3 tb(32, 8);
    wprep_kernel<<<dim3(96, 32), tb>>>(Wqkv, 3*NC, wq);
    wprep_kernel<<<dim3(32, 32), tb>>>(Wout,   NC, wo);
    prefix_fill_kernel<<<224, 256>>>(pk, pv);
    xprep_kernel<<<NROWS*(NC/2)/256, 256>>>(x);

    mma_gemm_kernel<0><<<dim3(24, 32), 256, GEMM_SMEM>>>(xh, wq, bqkv, nullptr);
    attn_kernel<<<dim3(16, 32), 256, ATTN_SMEM>>>();
    mma_gemm_kernel<1><<<dim3(8, 32), 256, GEMM_SMEM>>>(ath, wo, bout, out);
}

// round 15
// speedup vs baseline: 1.9955x; 1.0014x over previous
#include <cuda_runtime.h>
#include <cuda_bf16.h>
#include <cuda_fp16.h>
#include <cstdint>

// Problem constants
#define NB 2
#define NT 2048
#define NC 1024
#define NH 16
#define ND 64
#define NP 16
#define NS 2064      // NP + NT
#define SPAD 2112    // 33 chunks of 64
#define NROWS 4096   // NB * NT

// ---------------------------------------------------------------------------
// Scratch (allocation-free: __device__ globals). Packed-pair u32 arrays.
// ---------------------------------------------------------------------------
__device__ uint32_t g_xh[(size_t)NROWS*NC/2];        // x fp16 pairs [row][512]
__device__ uint32_t g_ath[(size_t)NROWS*NC/2];       // attention out fp16 pairs
__device__ uint32_t g_qh[NB*NH*NT*ND/2];             // q fp16 (x0.125)
__device__ uint32_t g_kh[NB*NH*SPAD*ND/2];           // k fp16
__device__ uint32_t g_vh[NB*NH*SPAD*ND/2];           // v fp16
// Pre-transposed fp16 weights, [N][K=1024]
__device__ __half g_wqkv[3*NC*NC];
__device__ __half g_wout[NC*NC];

// ---------------------------------------------------------------------------
// Helpers (family-agnostic: ldmatrix / mma.sync / cp.async only)
// ---------------------------------------------------------------------------
__device__ __forceinline__ uint32_t smem_u32(const void* p) {
    uint32_t a;
    asm("{ .reg .u64 t; cvta.to.shared.u64 t, %1; cvt.u32.u64 %0, t; }" : "=r"(a) : "l"(p));
    return a;
}

#define CP_ASYNC16(dst, src) \
    asm volatile("cp.async.cg.shared.global [%0], [%1], 16;" :: "r"(dst), "l"(src) : "memory")
#define CP_COMMIT() asm volatile("cp.async.commit_group;" ::: "memory")
#define CP_WAIT0()  asm volatile("cp.async.wait_group 0;" ::: "memory")
#define CP_WAIT1()  asm volatile("cp.async.wait_group 1;" ::: "memory")

#define SW128(o) ((o) ^ (((o) >> 3) & 0x70))
__device__ __forceinline__ uint32_t swz(uint32_t base, uint32_t off) {
    return base + SW128(off);
}

__device__ __forceinline__ void ldsm_x4(uint32_t& r0, uint32_t& r1, uint32_t& r2, uint32_t& r3,
                                        uint32_t addr) {
    asm volatile("ldmatrix.sync.aligned.m8n8.x4.shared.b16 {%0,%1,%2,%3}, [%4];"
                 : "=r"(r0), "=r"(r1), "=r"(r2), "=r"(r3) : "r"(addr));
}
__device__ __forceinline__ void ldsm_x4t(uint32_t& r0, uint32_t& r1, uint32_t& r2, uint32_t& r3,
                                         uint32_t addr) {
    asm volatile("ldmatrix.sync.aligned.m8n8.x4.trans.shared.b16 {%0,%1,%2,%3}, [%4];"
                 : "=r"(r0), "=r"(r1), "=r"(r2), "=r"(r3) : "r"(addr));
}

__device__ __forceinline__ void mma_f16(float* d, const uint32_t* a, const uint32_t* b) {
    asm volatile("mma.sync.aligned.m16n8k16.row.col.f32.f16.f16.f32 "
                 "{%0,%1,%2,%3}, {%4,%5,%6,%7}, {%8,%9}, {%0,%1,%2,%3};"
                 : "+f"(d[0]), "+f"(d[1]), "+f"(d[2]), "+f"(d[3])
                 : "r"(a[0]), "r"(a[1]), "r"(a[2]), "r"(a[3]), "r"(b[0]), "r"(b[1]));
}

__device__ __forceinline__ uint32_t h2pack(float a, float b) {
    __half2 h = __floats2half2_rn(a, b);
    return *reinterpret_cast<uint32_t*>(&h);
}

// ---------------------------------------------------------------------------
// Fused prep: one launch covering
//   [0, 3072)            Wqkv transpose tiles (96 x 32 grid of 32x32 tiles)
//   [3072, 4096)         Wout transpose tiles (32 x 32)
//   [4096, 4352)         prefix fill + K/V pad rows (65536 threads)
//   [4352, 12544)        xprep: fp32 x -> fp16 pairs
// ---------------------------------------------------------------------------
#define PREP_WQ   3072
#define PREP_WO   1024
#define PREP_PF   256
#define PREP_XP   8192
#define PREP_BLOCKS (PREP_WQ + PREP_WO + PREP_PF + PREP_XP)

__global__ __launch_bounds__(256) void prep_kernel(
        const float* __restrict__ x,
        const float* __restrict__ pk,
        const float* __restrict__ pv,
        const float* __restrict__ Wqkv,
        const float* __restrict__ Wout) {
    const int blk = blockIdx.x;
    const int tid = threadIdx.x;

    if (blk < PREP_WQ + PREP_WO) {
        // ---- weight transpose + fp16 convert ----
        __shared__ float tile[32][33];
        const float* W;
        __half* Wt;
        int N, tb;
        if (blk < PREP_WQ) { W = Wqkv; Wt = g_wqkv; N = 3*NC; tb = blk; }
        else               { W = Wout; Wt = g_wout; N = NC;   tb = blk - PREP_WQ; }
        const int ntx = N >> 5;
        const int n0 = (tb % ntx) * 32, k0 = (tb / ntx) * 32;
        const int tx = tid & 31, ty = tid >> 5;
#pragma unroll
        for (int i = 0; i < 32; i += 8)
            tile[ty + i][tx] = W[(size_t)(k0 + ty + i) * N + n0 + tx];
        __syncthreads();
#pragma unroll
        for (int i = 0; i < 32; i += 8)
            Wt[(size_t)(n0 + ty + i) * NC + k0 + tx] = __float2half_rn(tile[tx][ty + i]);
    } else if (blk < PREP_WQ + PREP_WO + PREP_PF) {
        // ---- prefix fill + pad rows ----
        int idx = (blk - PREP_WQ - PREP_WO) * 256 + tid;
        if (idx < NH*NP*32) {
            int h = idx >> 9;
            int p = (idx >> 5) & (NP - 1);
            int dp = idx & 31;
            const float* kp = pk + ((size_t)h * NP + p) * ND + 2*dp;
            const float* vp = pv + ((size_t)h * NP + p) * ND + 2*dp;
            uint32_t kh = h2pack(kp[0], kp[1]);
            uint32_t vh = h2pack(vp[0], vp[1]);
#pragma unroll
            for (int b = 0; b < NB; b++) {
                size_t o = ((size_t)(b*NH + h) * SPAD + p) * 32 + dp;
                g_kh[o] = kh; g_vh[o] = vh;
            }
        } else {
            int j = idx - NH*NP*32;
            if (j < NB*NH*48*32) {
                int bh = j / (48*32);
                int rem = j % (48*32);
                int r = NS + (rem >> 5);
                int dp = rem & 31;
                size_t o = ((size_t)bh * SPAD + r) * 32 + dp;
                g_kh[o] = 0; g_vh[o] = 0;
            }
        }
    } else {
        // ---- xprep ----
        int idx = (blk - PREP_WQ - PREP_WO - PREP_PF) * 256 + tid;
        float2 v = *(const float2*)(x + 2 * (size_t)idx);
        g_xh[idx] = h2pack(v.x, v.y);
    }
}

// ---------------------------------------------------------------------------
// mma.sync GEMM, single-pass fp16: C = A @ B^T.
// CTA 128x128, 256 threads = 8 warps (4m x 2n), warp tile 32x64.
// K chunks of 64, 3-stage cp.async pipeline: (A 16K | B 16K) x3 = 96KB.
// ONE __syncthreads per chunk. 2 CTAs/SM.
// MODE 0: epilogue scatters q fp16 (x0.125) / k fp16 / v fp16.
// MODE 1: epilogue adds bias, writes fp32 d_out.
// ---------------------------------------------------------------------------
#define GEMM_SMEM (3*32768 + 1024)
#define NCH 16

template<int MODE>
__global__ __launch_bounds__(256, 2) void mma_gemm_kernel(
        const uint32_t* __restrict__ A_g,
        const __half* __restrict__ W,
        const float* __restrict__ bias,
        float* __restrict__ out) {
    extern __shared__ char dsm[];
    const uint32_t sb = (smem_u32(dsm) + 1023u) & ~1023u;

    const int tid = threadIdx.x;
    const int lane = tid & 31;
    const int wm = (tid >> 5) & 3;          // warp m (0..3), rows 32*wm
    const int wn = tid >> 7;                // warp n (0..1), cols 64*wn
    const int r0 = blockIdx.y * 128;
    const int c0 = blockIdx.x * 128;

    const uint32_t a_off = (uint32_t)((32*wm + (lane & 15)) * 128 + (lane >> 4) * 16);
    const uint32_t b_off = (uint32_t)((64*wn + ((lane >> 4) & 1) * 8 + (lane & 7)) * 128
                                      + ((lane >> 3) & 1) * 16);
    const int ldrow = tid >> 3;             // 0..31
    const int ldc8  = (tid & 7) * 8;        // fp16-element col offset

    float acc[2][8][4];
#pragma unroll
    for (int mf = 0; mf < 2; mf++)
#pragma unroll
        for (int ng = 0; ng < 8; ng++)
#pragma unroll
            for (int c = 0; c < 4; c++) acc[mf][ng][c] = 0.f;

    auto loadStage = [&](int ch, uint32_t bb) {
#pragma unroll
        for (int it = 0; it < 4; ++it) {
            int row = ldrow + it * 32;
            uint32_t off = SW128((uint32_t)(row * 128 + ldc8 * 2));
            size_t ga = (size_t)(r0 + row) * (NC/2) + (ch * 64 + ldc8) / 2;
            CP_ASYNC16(bb + off, A_g + ga);
            size_t gb = (size_t)(c0 + row) * NC + ch * 64 + ldc8;
            CP_ASYNC16(bb + 16384u + off, W + gb);
        }
    };

    loadStage(0, sb);
    CP_COMMIT();
    loadStage(1, sb + 32768u);
    CP_COMMIT();

    for (int ch = 0; ch < NCH; ++ch) {
        if (ch == NCH - 1) { CP_WAIT0(); } else { CP_WAIT1(); }
        __syncthreads();    // chunk ch visible to all; all warps done with ch-1
        if (ch + 2 < NCH) {
            loadStage(ch + 2, sb + (uint32_t)((ch + 2) % 3) * 32768u);
            CP_COMMIT();
        }

        const uint32_t base = sb + (uint32_t)(ch % 3) * 32768u;
        const uint32_t bA = base, bB = base + 16384u;
#pragma unroll
        for (int kk = 0; kk < 4; ++kk) {
            uint32_t Af[2][4];
#pragma unroll
            for (int mf = 0; mf < 2; mf++) {
                uint32_t o = a_off + kk * 32 + mf * 2048;
                ldsm_x4(Af[mf][0], Af[mf][1], Af[mf][2], Af[mf][3], swz(bA, o));
            }
            uint32_t Bf[4][4];
#pragma unroll
            for (int g = 0; g < 4; ++g) {
                uint32_t o = b_off + g * 2048 + kk * 32;
                ldsm_x4(Bf[g][0], Bf[g][1], Bf[g][2], Bf[g][3], swz(bB, o));
            }
            // 16 independent MMAs
#pragma unroll
            for (int g = 0; g < 4; ++g)
#pragma unroll
                for (int mf = 0; mf < 2; mf++) {
                    mma_f16(acc[mf][2*g],   Af[mf], Bf[g]);
                    mma_f16(acc[mf][2*g+1], Af[mf], Bf[g] + 2);
                }
        }
    }

    // ---- epilogue ----
    const int g4 = lane >> 2, t4 = lane & 3;
    const int colb = c0 + 64 * wn;
    const int which = colb >> 10;               // MODE 0 only
    const int hh = (colb >> 6) & (NH - 1);
#pragma unroll
    for (int ng = 0; ng < 8; ++ng) {
        const int col = colb + 8 * ng + 2 * t4;
        const float b0v = bias[col], b1v = bias[col + 1];
#pragma unroll
        for (int mf = 0; mf < 2; mf++) {
            const int row = r0 + 32 * wm + 16 * mf + g4;
            const float* ac = acc[mf][ng];
            if (MODE == 1) {
                float2 v0 = make_float2(ac[0] + b0v, ac[1] + b1v);
                float2 v1 = make_float2(ac[2] + b0v, ac[3] + b1v);
                *(float2*)&out[(size_t)row * NC + col] = v0;
                *(float2*)&out[(size_t)(row + 8) * NC + col] = v1;
            } else {
                const int dp = (col & (ND - 1)) >> 1;
#pragma unroll
                for (int rr = 0; rr < 2; rr++) {
                    const int r = row + 8*rr;
                    const int b = r >> 11, t = r & (NT - 1);
                    const int bh = b * NH + hh;
                    float x = ac[2*rr] + b0v, y = ac[2*rr+1] + b1v;
                    if (which == 0) {
                        size_t o = ((size_t)bh * NT + t) * 32 + dp;
                        g_qh[o] = h2pack(x * 0.125f, y * 0.125f);
                    } else if (which == 1) {
                        size_t o = ((size_t)bh * SPAD + NP + t) * 32 + dp;
                        g_kh[o] = h2pack(x, y);
                    } else {
                        size_t o = ((size_t)bh * SPAD + NP + t) * 32 + dp;
                        g_vh[o] = h2pack(x, y);
                    }
                }
            }
        }
    }
}

// ---------------------------------------------------------------------------
// Tensor-core flash attention, single-pass fp16 QK, fp16 PV.
// 3-stage K/V pipeline, ONE __syncthreads per chunk.
// smem: Q 16K | 3 x (K 8K | V 8K) = 64K (+pad). 2 CTAs/SM.
// ---------------------------------------------------------------------------
#define ATTN_SMEM (16384 + 3*16384 + 1024)
#define NCHUNK 33

__global__ __launch_bounds__(256, 2) void attn_kernel() {
    extern __shared__ char dsm[];
    const uint32_t sb  = (smem_u32(dsm) + 1023u) & ~1023u;
    const uint32_t sQ = sb;
    const uint32_t sBuf0 = sb + 16384u;       // 3 bufs, each: K 8K | V 8K

    const int bh = blockIdx.y;
    const int q0 = blockIdx.x * 128;
    const int b = bh >> 4, h = bh & (NH - 1);
    const int tid = threadIdx.x;
    const int lane = tid & 31;
    const int wid = tid >> 5;

    const uint32_t* Qp  = g_qh + ((size_t)bh * NT + q0) * 32;
    const uint32_t* Khp = g_kh + (size_t)bh * SPAD * 32;
    const uint32_t* Vhp = g_vh + (size_t)bh * SPAD * 32;

    const uint32_t a_off = (uint32_t)((16*wid + (lane & 15)) * 128 + (lane >> 4) * 16);
    const uint32_t b_off = (uint32_t)((((lane >> 4) & 1) * 8 + (lane & 7)) * 128
                                      + ((lane >> 3) & 1) * 16);
    const uint32_t v_off = (uint32_t)((lane & 15) * 128 + (lane >> 4) * 16);

    auto loadChunk = [&](int ci, uint32_t bb) {
#pragma unroll
        for (int it = 0; it < 4; ++it) {
            int idx = tid + it * 256;           // 0..1023
            int ten = idx >> 9;                 // 0 K, 1 V
            int r = (idx & 511) >> 3;
            int seg = idx & 7;
            const uint32_t* base = ten ? Vhp : Khp;
            const uint32_t* src = base + (size_t)(ci * 64 + r) * 32 + seg * 4;
            uint32_t dst = bb + (uint32_t)ten * 8192u + SW128((uint32_t)(r * 128 + seg * 16));
            CP_ASYNC16(dst, src);
        }
    };

    // Q load folded into group 0
#pragma unroll
    for (int it = 0; it < 4; ++it) {
        int idx = tid + it * 256;
        int r = idx >> 3;
        int seg = idx & 7;
        const uint32_t* src = Qp + (size_t)r * 32 + seg * 4;
        uint32_t dst = sQ + SW128((uint32_t)(r * 128 + seg * 16));
        CP_ASYNC16(dst, src);
    }
    loadChunk(0, sBuf0);
    CP_COMMIT();
    loadChunk(1, sBuf0 + 16384u);
    CP_COMMIT();

    float O[8][4];
#pragma unroll
    for (int g = 0; g < 8; g++)
#pragma unroll
        for (int c = 0; c < 4; c++) O[g][c] = 0.f;
    float m0 = -1e30f, m1 = -1e30f, l0 = 0.f, l1 = 0.f;

    for (int ci = 0; ci < NCHUNK; ++ci) {
        if (ci == NCHUNK - 1) { CP_WAIT0(); } else { CP_WAIT1(); }
        __syncthreads();    // chunk ci (and Q) visible; all warps done with ci-1
        if (ci + 2 < NCHUNK) {
            loadChunk(ci + 2, sBuf0 + (uint32_t)((ci + 2) % 3) * 16384u);
            CP_COMMIT();
        }

        const uint32_t buf = sBuf0 + (uint32_t)(ci % 3) * 16384u;
        const uint32_t bK = buf, bV = buf + 8192u;

        // ---- S = Q K^T (single-pass fp16) ----
        float S[8][4];
#pragma unroll
        for (int g = 0; g < 8; g++)
#pragma unroll
            for (int c = 0; c < 4; c++) S[g][c] = 0.f;
#pragma unroll
        for (int kk = 0; kk < 4; ++kk) {
            uint32_t Af[4];
            ldsm_x4(Af[0], Af[1], Af[2], Af[3], swz(sQ, a_off + kk * 32));
#pragma unroll
            for (int gp = 0; gp < 2; ++gp) {
                uint32_t K0[4], K1[4];
                uint32_t o0 = b_off + (2*gp) * 2048 + kk * 32;
                uint32_t o1 = b_off + (2*gp+1) * 2048 + kk * 32;
                ldsm_x4(K0[0], K0[1], K0[2], K0[3], swz(bK, o0));
                ldsm_x4(K1[0], K1[1], K1[2], K1[3], swz(bK, o1));
                mma_f16(S[4*gp],   Af, K0); mma_f16(S[4*gp+1], Af, K0 + 2);
                mma_f16(S[4*gp+2], Af, K1); mma_f16(S[4*gp+3], Af, K1 + 2);
            }
        }

        // ---- tail mask (chunk 32: only cols 0..15 valid => frags g>=2) ----
        if (ci == NCHUNK - 1) {
#pragma unroll
            for (int g = 2; g < 8; g++)
#pragma unroll
                for (int c = 0; c < 4; c++) S[g][c] = -1e30f;
        }

        // ---- online softmax ----
        float tm0 = -1e30f, tm1 = -1e30f;
#pragma unroll
        for (int g = 0; g < 8; g++) {
            tm0 = fmaxf(tm0, fmaxf(S[g][0], S[g][1]));
            tm1 = fmaxf(tm1, fmaxf(S[g][2], S[g][3]));
        }
        tm0 = fmaxf(tm0, __shfl_xor_sync(0xffffffffu, tm0, 1));
        tm0 = fmaxf(tm0, __shfl_xor_sync(0xffffffffu, tm0, 2));
        tm1 = fmaxf(tm1, __shfl_xor_sync(0xffffffffu, tm1, 1));
        tm1 = fmaxf(tm1, __shfl_xor_sync(0xffffffffu, tm1, 2));
        float mn0 = fmaxf(m0, tm0), mn1 = fmaxf(m1, tm1);
        float al0 = __expf(m0 - mn0), al1 = __expf(m1 - mn1);
        float s0 = 0.f, s1 = 0.f;
#pragma unroll
        for (int g = 0; g < 8; g++) {
            S[g][0] = __expf(S[g][0] - mn0);
            S[g][1] = __expf(S[g][1] - mn0);
            S[g][2] = __expf(S[g][2] - mn1);
            S[g][3] = __expf(S[g][3] - mn1);
            s0 += S[g][0] + S[g][1];
            s1 += S[g][2] + S[g][3];
        }
        s0 += __shfl_xor_sync(0xffffffffu, s0, 1);
        s0 += __shfl_xor_sync(0xffffffffu, s0, 2);
        s1 += __shfl_xor_sync(0xffffffffu, s1, 1);
        s1 += __shfl_xor_sync(0xffffffffu, s1, 2);
        l0 = l0 * al0 + s0; l1 = l1 * al1 + s1;
        m0 = mn0; m1 = mn1;
#pragma unroll
        for (int g = 0; g < 8; g++) {
            O[g][0] *= al0; O[g][1] *= al0;
            O[g][2] *= al1; O[g][3] *= al1;
        }

        // ---- pack P to fp16 A-frags ----
        uint32_t pa[4][4];
#pragma unroll
        for (int kk = 0; kk < 4; ++kk) {
            pa[kk][0] = h2pack(S[2*kk][0],   S[2*kk][1]);
            pa[kk][1] = h2pack(S[2*kk][2],   S[2*kk][3]);
            pa[kk][2] = h2pack(S[2*kk+1][0], S[2*kk+1][1]);
            pa[kk][3] = h2pack(S[2*kk+1][2], S[2*kk+1][3]);
        }

        // ---- O += P V ----
#pragma unroll
        for (int kk = 0; kk < 4; ++kk) {
#pragma unroll
            for (int gg = 0; gg < 4; ++gg) {
                uint32_t Vb[4];
                uint32_t o = v_off + kk * 2048 + gg * 32;
                ldsm_x4t(Vb[0], Vb[1], Vb[2], Vb[3], swz(bV, o));
                mma_f16(O[2*gg],   pa[kk], Vb);
                mma_f16(O[2*gg+1], pa[kk], Vb + 2);
            }
        }
    }

    // ---- epilogue: normalize, pack fp16, write g_ath ----
    const float inv0 = 1.f / l0, inv1 = 1.f / l1;
    const int r = lane >> 2;
    const int row0 = q0 + 16*wid + r;
#pragma unroll
    for (int g = 0; g < 8; g++) {
        const int dp = h * 32 + 4*g + (lane & 3);   // pair index within row
        size_t o0 = (size_t)(b*NT + row0) * 512 + dp;
        g_ath[o0] = h2pack(O[g][0] * inv0, O[g][1] * inv0);
        size_t o1 = (size_t)(b*NT + row0 + 8) * 512 + dp;
        g_ath[o1] = h2pack(O[g][2] * inv1, O[g][3] * inv1);
    }
}

// ---------------------------------------------------------------------------
// Launch
// ---------------------------------------------------------------------------
extern "C" void kernel_launch(void* const* d_in, const int* in_sizes, int n_in,
                              void* d_out, int out_size) {
    const float* x    = (const float*)d_in[0];
    const float* pk   = (const float*)d_in[1];
    const float* pv   = (const float*)d_in[2];
    const float* Wqkv = (const float*)d_in[3];
    const float* bqkv = (const float*)d_in[4];
    const float* Wout = (const float*)d_in[5];
    const float* bout = (const float*)d_in[6];
    float* out = (float*)d_out;

    cudaFuncSetAttribute(attn_kernel,
                         cudaFuncAttributeMaxDynamicSharedMemorySize, ATTN_SMEM);
    cudaFuncSetAttribute(mma_gemm_kernel<0>,
                         cudaFuncAttributeMaxDynamicSharedMemorySize, GEMM_SMEM);
    cudaFuncSetAttribute(mma_gemm_kernel<1>,
                         cudaFuncAttributeMaxDynamicSharedMemorySize, GEMM_SMEM);

    __half *wq, *wo;
    uint32_t *xh, *ath;
    cudaGetSymbolAddress((void**)&wq,  g_wqkv);
    cudaGetSymbolAddress((void**)&wo,  g_wout);
    cudaGetSymbolAddress((void**)&xh,  g_xh);
    cudaGetSymbolAddress((void**)&ath, g_ath);

    prep_kernel<<<PREP_BLOCKS, 256>>>(x, pk, pv, Wqkv, Wout);
    mma_gemm_kernel<0><<<dim3(24, 32), 256, GEMM_SMEM>>>(xh, wq, bqkv, nullptr);
    attn_kernel<<<dim3(16, 32), 256, ATTN_SMEM>>>();
    mma_gemm_kernel<1><<<dim3(8, 32), 256, GEMM_SMEM>>>(ath, wo, bout, out);
}

// round 16
// speedup vs baseline: 2.1034x; 1.0541x over previous
#include <cuda_runtime.h>
#include <cuda_bf16.h>
#include <cuda_fp16.h>
#include <cstdint>

// Problem constants
#define NB 2
#define NT 2048
#define NC 1024
#define NH 16
#define ND 64
#define NP 16
#define NS 2064      // NP + NT
#define SPAD 2112    // 33 chunks of 64
#define NROWS 4096   // NB * NT

// q pre-scale: 0.125 * log2(e), so scores come out of QK in log2 domain
#define QSCALE 0.18033688011112042f

// ---------------------------------------------------------------------------
// Scratch (allocation-free: __device__ globals). Packed-pair u32 arrays.
// ---------------------------------------------------------------------------
__device__ uint32_t g_xh[(size_t)NROWS*NC/2];        // x fp16 pairs [row][512]
__device__ uint32_t g_ath[(size_t)NROWS*NC/2];       // attention out fp16 pairs
__device__ uint32_t g_qh[NB*NH*NT*ND/2];             // q fp16 (xQSCALE)
__device__ uint32_t g_kh[NB*NH*SPAD*ND/2];           // k fp16
__device__ uint32_t g_vh[NB*NH*SPAD*ND/2];           // v fp16
// Pre-transposed fp16 weights, [N][K=1024]
__device__ __half g_wqkv[3*NC*NC];
__device__ __half g_wout[NC*NC];

// ---------------------------------------------------------------------------
// Helpers (family-agnostic: ldmatrix / mma.sync / cp.async only)
// ---------------------------------------------------------------------------
__device__ __forceinline__ uint32_t smem_u32(const void* p) {
    uint32_t a;
    asm("{ .reg .u64 t; cvta.to.shared.u64 t, %1; cvt.u32.u64 %0, t; }" : "=r"(a) : "l"(p));
    return a;
}

#define CP_ASYNC16(dst, src) \
    asm volatile("cp.async.cg.shared.global [%0], [%1], 16;" :: "r"(dst), "l"(src) : "memory")
#define CP_COMMIT() asm volatile("cp.async.commit_group;" ::: "memory")
#define CP_WAIT0()  asm volatile("cp.async.wait_group 0;" ::: "memory")
#define CP_WAIT1()  asm volatile("cp.async.wait_group 1;" ::: "memory")

#define SW128(o) ((o) ^ (((o) >> 3) & 0x70))
__device__ __forceinline__ uint32_t swz(uint32_t base, uint32_t off) {
    return base + SW128(off);
}

__device__ __forceinline__ void ldsm_x4(uint32_t& r0, uint32_t& r1, uint32_t& r2, uint32_t& r3,
                                        uint32_t addr) {
    asm volatile("ldmatrix.sync.aligned.m8n8.x4.shared.b16 {%0,%1,%2,%3}, [%4];"
                 : "=r"(r0), "=r"(r1), "=r"(r2), "=r"(r3) : "r"(addr));
}
__device__ __forceinline__ void ldsm_x4t(uint32_t& r0, uint32_t& r1, uint32_t& r2, uint32_t& r3,
                                         uint32_t addr) {
    asm volatile("ldmatrix.sync.aligned.m8n8.x4.trans.shared.b16 {%0,%1,%2,%3}, [%4];"
                 : "=r"(r0), "=r"(r1), "=r"(r2), "=r"(r3) : "r"(addr));
}

__device__ __forceinline__ void mma_f16(float* d, const uint32_t* a, const uint32_t* b) {
    asm volatile("mma.sync.aligned.m16n8k16.row.col.f32.f16.f16.f32 "
                 "{%0,%1,%2,%3}, {%4,%5,%6,%7}, {%8,%9}, {%0,%1,%2,%3};"
                 : "+f"(d[0]), "+f"(d[1]), "+f"(d[2]), "+f"(d[3])
                 : "r"(a[0]), "r"(a[1]), "r"(a[2]), "r"(a[3]), "r"(b[0]), "r"(b[1]));
}

__device__ __forceinline__ uint32_t h2pack(float a, float b) {
    __half2 h = __floats2half2_rn(a, b);
    return *reinterpret_cast<uint32_t*>(&h);
}

// ---------------------------------------------------------------------------
// Prep launch 1: Wqkv transpose tiles [0,3072) + xprep float4 [3072,7168)
// (only the gemm0 dependencies; Wout/prefix are tail-filled into gemm0)
// ---------------------------------------------------------------------------
#define PREP_WQ   3072
#define PREP_XP   4096
#define PREP_BLOCKS (PREP_WQ + PREP_XP)

__global__ __launch_bounds__(256) void prep_kernel(
        const float* __restrict__ x,
        const float* __restrict__ Wqkv) {
    const int blk = blockIdx.x;
    const int tid = threadIdx.x;

    if (blk < PREP_WQ) {
        __shared__ float tile[32][33];
        const int N = 3*NC;
        const int ntx = N >> 5;
        const int n0 = (blk % ntx) * 32, k0 = (blk / ntx) * 32;
        const int tx = tid & 31, ty = tid >> 5;
#pragma unroll
        for (int i = 0; i < 32; i += 8)
            tile[ty + i][tx] = Wqkv[(size_t)(k0 + ty + i) * N + n0 + tx];
        __syncthreads();
#pragma unroll
        for (int i = 0; i < 32; i += 8)
            g_wqkv[(size_t)(n0 + ty + i) * NC + k0 + tx] = __float2half_rn(tile[tx][ty + i]);
    } else {
        // xprep: 2 pairs (float4) per thread
        int idx = (blk - PREP_WQ) * 256 + tid;      // float4 index
        float4 v = *(const float4*)(x + 4 * (size_t)idx);
        g_xh[2*idx]     = h2pack(v.x, v.y);
        g_xh[2*idx + 1] = h2pack(v.z, v.w);
    }
}

// ---------------------------------------------------------------------------
// mma.sync GEMM, single-pass fp16: C = A @ B^T.
// CTA 128x128, 256 threads = 8 warps (4m x 2n), warp tile 32x64.
// K chunks of 64, 3-stage cp.async pipeline: (A 16K | B 16K) x3 = 96KB.
// ONE __syncthreads per chunk. 2 CTAs/SM.
// MODE 0: 1D grid 2048 blocks: [0,768) GEMM tiles (epilogue scatters q/k/v),
//         [768,1792) Wout transpose (tail fill), [1792,2048) prefix fill.
// MODE 1: 2D grid, epilogue adds bias, writes fp32 d_out.
// ---------------------------------------------------------------------------
#define GEMM_SMEM (3*32768 + 1024)
#define NCH 16
#define G0_TILES 768
#define G0_WO    1024

template<int MODE>
__global__ __launch_bounds__(256, 2) void mma_gemm_kernel(
        const uint32_t* __restrict__ A_g,
        const __half* __restrict__ W,
        const float* __restrict__ bias,
        float* __restrict__ out,
        const float* __restrict__ Wout,
        const float* __restrict__ pk,
        const float* __restrict__ pv) {
    extern __shared__ char dsm[];
    const int tid = threadIdx.x;

    int bx, by;
    if (MODE == 0) {
        const int bid = blockIdx.x;
        if (bid >= G0_TILES) {
            if (bid < G0_TILES + G0_WO) {
                // ---- Wout transpose + fp16 (tail fill) ----
                float (*tile)[33] = reinterpret_cast<float(*)[33]>(dsm);
                const int tb = bid - G0_TILES;
                const int n0 = (tb & 31) * 32, k0 = (tb >> 5) * 32;
                const int tx = tid & 31, ty = tid >> 5;
#pragma unroll
                for (int i = 0; i < 32; i += 8)
                    tile[ty + i][tx] = Wout[(size_t)(k0 + ty + i) * NC + n0 + tx];
                __syncthreads();
#pragma unroll
                for (int i = 0; i < 32; i += 8)
                    g_wout[(size_t)(n0 + ty + i) * NC + k0 + tx] =
                        __float2half_rn(tile[tx][ty + i]);
            } else {
                // ---- prefix fill + K/V pad rows (tail fill) ----
                int idx = (bid - G0_TILES - G0_WO) * 256 + tid;
                if (idx < NH*NP*32) {
                    int h = idx >> 9;
                    int p = (idx >> 5) & (NP - 1);
                    int dp = idx & 31;
                    const float* kp = pk + ((size_t)h * NP + p) * ND + 2*dp;
                    const float* vp = pv + ((size_t)h * NP + p) * ND + 2*dp;
                    uint32_t kh = h2pack(kp[0], kp[1]);
                    uint32_t vh = h2pack(vp[0], vp[1]);
#pragma unroll
                    for (int b = 0; b < NB; b++) {
                        size_t o = ((size_t)(b*NH + h) * SPAD + p) * 32 + dp;
                        g_kh[o] = kh; g_vh[o] = vh;
                    }
                } else {
                    int j = idx - NH*NP*32;
                    if (j < NB*NH*48*32) {
                        int bh = j / (48*32);
                        int rem = j % (48*32);
                        int r = NS + (rem >> 5);
                        int dp = rem & 31;
                        size_t o = ((size_t)bh * SPAD + r) * 32 + dp;
                        g_kh[o] = 0; g_vh[o] = 0;
                    }
                }
            }
            return;
        }
        bx = bid % 24;
        by = bid / 24;
    } else {
        bx = blockIdx.x;
        by = blockIdx.y;
    }

    const uint32_t sb = (smem_u32(dsm) + 1023u) & ~1023u;
    const int lane = tid & 31;
    const int wm = (tid >> 5) & 3;          // warp m (0..3), rows 32*wm
    const int wn = tid >> 7;                // warp n (0..1), cols 64*wn
    const int r0 = by * 128;
    const int c0 = bx * 128;

    const uint32_t a_off = (uint32_t)((32*wm + (lane & 15)) * 128 + (lane >> 4) * 16);
    const uint32_t b_off = (uint32_t)((64*wn + ((lane >> 4) & 1) * 8 + (lane & 7)) * 128
                                      + ((lane >> 3) & 1) * 16);
    const int ldrow = tid >> 3;             // 0..31
    const int ldc8  = (tid & 7) * 8;        // fp16-element col offset

    float acc[2][8][4];
#pragma unroll
    for (int mf = 0; mf < 2; mf++)
#pragma unroll
        for (int ng = 0; ng < 8; ng++)
#pragma unroll
            for (int c = 0; c < 4; c++) acc[mf][ng][c] = 0.f;

    auto loadStage = [&](int ch, uint32_t bb) {
#pragma unroll
        for (int it = 0; it < 4; ++it) {
            int row = ldrow + it * 32;
            uint32_t off = SW128((uint32_t)(row * 128 + ldc8 * 2));
            size_t ga = (size_t)(r0 + row) * (NC/2) + (ch * 64 + ldc8) / 2;
            CP_ASYNC16(bb + off, A_g + ga);
            size_t gb = (size_t)(c0 + row) * NC + ch * 64 + ldc8;
            CP_ASYNC16(bb + 16384u + off, W + gb);
        }
    };

    loadStage(0, sb);
    CP_COMMIT();
    loadStage(1, sb + 32768u);
    CP_COMMIT();

    for (int ch = 0; ch < NCH; ++ch) {
        if (ch == NCH - 1) { CP_WAIT0(); } else { CP_WAIT1(); }
        __syncthreads();    // chunk ch visible to all; all warps done with ch-1
        if (ch + 2 < NCH) {
            loadStage(ch + 2, sb + (uint32_t)((ch + 2) % 3) * 32768u);
            CP_COMMIT();
        }

        const uint32_t base = sb + (uint32_t)(ch % 3) * 32768u;
        const uint32_t bA = base, bB = base + 16384u;
#pragma unroll
        for (int kk = 0; kk < 4; ++kk) {
            uint32_t Af[2][4];
#pragma unroll
            for (int mf = 0; mf < 2; mf++) {
                uint32_t o = a_off + kk * 32 + mf * 2048;
                ldsm_x4(Af[mf][0], Af[mf][1], Af[mf][2], Af[mf][3], swz(bA, o));
            }
            uint32_t Bf[4][4];
#pragma unroll
            for (int g = 0; g < 4; ++g) {
                uint32_t o = b_off + g * 2048 + kk * 32;
                ldsm_x4(Bf[g][0], Bf[g][1], Bf[g][2], Bf[g][3], swz(bB, o));
            }
            // 16 independent MMAs
#pragma unroll
            for (int g = 0; g < 4; ++g)
#pragma unroll
                for (int mf = 0; mf < 2; mf++) {
                    mma_f16(acc[mf][2*g],   Af[mf], Bf[g]);
                    mma_f16(acc[mf][2*g+1], Af[mf], Bf[g] + 2);
                }
        }
    }

    // ---- epilogue ----
    const int g4 = lane >> 2, t4 = lane & 3;
    const int colb = c0 + 64 * wn;
    const int which = colb >> 10;               // MODE 0 only
    const int hh = (colb >> 6) & (NH - 1);
#pragma unroll
    for (int ng = 0; ng < 8; ++ng) {
        const int col = colb + 8 * ng + 2 * t4;
        const float b0v = bias[col], b1v = bias[col + 1];
#pragma unroll
        for (int mf = 0; mf < 2; mf++) {
            const int row = r0 + 32 * wm + 16 * mf + g4;
            const float* ac = acc[mf][ng];
            if (MODE == 1) {
                float2 v0 = make_float2(ac[0] + b0v, ac[1] + b1v);
                float2 v1 = make_float2(ac[2] + b0v, ac[3] + b1v);
                *(float2*)&out[(size_t)row * NC + col] = v0;
                *(float2*)&out[(size_t)(row + 8) * NC + col] = v1;
            } else {
                const int dp = (col & (ND - 1)) >> 1;
#pragma unroll
                for (int rr = 0; rr < 2; rr++) {
                    const int r = row + 8*rr;
                    const int b = r >> 11, t = r & (NT - 1);
                    const int bh = b * NH + hh;
                    float x = ac[2*rr] + b0v, y = ac[2*rr+1] + b1v;
                    if (which == 0) {
                        size_t o = ((size_t)bh * NT + t) * 32 + dp;
                        g_qh[o] = h2pack(x * QSCALE, y * QSCALE);
                    } else if (which == 1) {
                        size_t o = ((size_t)bh * SPAD + NP + t) * 32 + dp;
                        g_kh[o] = h2pack(x, y);
                    } else {
                        size_t o = ((size_t)bh * SPAD + NP + t) * 32 + dp;
                        g_vh[o] = h2pack(x, y);
                    }
                }
            }
        }
    }
}

// ---------------------------------------------------------------------------
// Tensor-core flash attention, single-pass fp16 QK (log2 domain), fp16 PV.
// 3-stage K/V pipeline, ONE __syncthreads per chunk. exp2-based softmax.
// smem: Q 16K | 3 x (K 8K | V 8K) = 64K (+pad). 2 CTAs/SM.
// ---------------------------------------------------------------------------
#define ATTN_SMEM (16384 + 3*16384 + 1024)
#define NCHUNK 33

__global__ __launch_bounds__(256, 2) void attn_kernel() {
    extern __shared__ char dsm[];
    const uint32_t sb  = (smem_u32(dsm) + 1023u) & ~1023u;
    const uint32_t sQ = sb;
    const uint32_t sBuf0 = sb + 16384u;       // 3 bufs, each: K 8K | V 8K

    const int bh = blockIdx.y;
    const int q0 = blockIdx.x * 128;
    const int b = bh >> 4, h = bh & (NH - 1);
    const int tid = threadIdx.x;
    const int lane = tid & 31;
    const int wid = tid >> 5;

    const uint32_t* Qp  = g_qh + ((size_t)bh * NT + q0) * 32;
    const uint32_t* Khp = g_kh + (size_t)bh * SPAD * 32;
    const uint32_t* Vhp = g_vh + (size_t)bh * SPAD * 32;

    const uint32_t a_off = (uint32_t)((16*wid + (lane & 15)) * 128 + (lane >> 4) * 16);
    const uint32_t b_off = (uint32_t)((((lane >> 4) & 1) * 8 + (lane & 7)) * 128
                                      + ((lane >> 3) & 1) * 16);
    const uint32_t v_off = (uint32_t)((lane & 15) * 128 + (lane >> 4) * 16);

    auto loadChunk = [&](int ci, uint32_t bb) {
#pragma unroll
        for (int it = 0; it < 4; ++it) {
            int idx = tid + it * 256;           // 0..1023
            int ten = idx >> 9;                 // 0 K, 1 V
            int r = (idx & 511) >> 3;
            int seg = idx & 7;
            const uint32_t* base = ten ? Vhp : Khp;
            const uint32_t* src = base + (size_t)(ci * 64 + r) * 32 + seg * 4;
            uint32_t dst = bb + (uint32_t)ten * 8192u + SW128((uint32_t)(r * 128 + seg * 16));
            CP_ASYNC16(dst, src);
        }
    };

    // Q load folded into group 0
#pragma unroll
    for (int it = 0; it < 4; ++it) {
        int idx = tid + it * 256;
        int r = idx >> 3;
        int seg = idx & 7;
        const uint32_t* src = Qp + (size_t)r * 32 + seg * 4;
        uint32_t dst = sQ + SW128((uint32_t)(r * 128 + seg * 16));
        CP_ASYNC16(dst, src);
    }
    loadChunk(0, sBuf0);
    CP_COMMIT();
    loadChunk(1, sBuf0 + 16384u);
    CP_COMMIT();

    float O[8][4];
#pragma unroll
    for (int g = 0; g < 8; g++)
#pragma unroll
        for (int c = 0; c < 4; c++) O[g][c] = 0.f;
    float m0 = -1e30f, m1 = -1e30f, l0 = 0.f, l1 = 0.f;

    for (int ci = 0; ci < NCHUNK; ++ci) {
        if (ci == NCHUNK - 1) { CP_WAIT0(); } else { CP_WAIT1(); }
        __syncthreads();    // chunk ci (and Q) visible; all warps done with ci-1
        if (ci + 2 < NCHUNK) {
            loadChunk(ci + 2, sBuf0 + (uint32_t)((ci + 2) % 3) * 16384u);
            CP_COMMIT();
        }

        const uint32_t buf = sBuf0 + (uint32_t)(ci % 3) * 16384u;
        const uint32_t bK = buf, bV = buf + 8192u;

        // ---- S = Q K^T (single-pass fp16, scores already in log2 domain) ----
        float S[8][4];
#pragma unroll
        for (int g = 0; g < 8; g++)
#pragma unroll
            for (int c = 0; c < 4; c++) S[g][c] = 0.f;
#pragma unroll
        for (int kk = 0; kk < 4; ++kk) {
            uint32_t Af[4];
            ldsm_x4(Af[0], Af[1], Af[2], Af[3], swz(sQ, a_off + kk * 32));
#pragma unroll
            for (int gp = 0; gp < 2; ++gp) {
                uint32_t K0[4], K1[4];
                uint32_t o0 = b_off + (2*gp) * 2048 + kk * 32;
                uint32_t o1 = b_off + (2*gp+1) * 2048 + kk * 32;
                ldsm_x4(K0[0], K0[1], K0[2], K0[3], swz(bK, o0));
                ldsm_x4(K1[0], K1[1], K1[2], K1[3], swz(bK, o1));
                mma_f16(S[4*gp],   Af, K0); mma_f16(S[4*gp+1], Af, K0 + 2);
                mma_f16(S[4*gp+2], Af, K1); mma_f16(S[4*gp+3], Af, K1 + 2);
            }
        }

        // ---- tail mask (chunk 32: only cols 0..15 valid => frags g>=2) ----
        if (ci == NCHUNK - 1) {
#pragma unroll
            for (int g = 2; g < 8; g++)
#pragma unroll
                for (int c = 0; c < 4; c++) S[g][c] = -1e30f;
        }

        // ---- online softmax (exp2 domain) ----
        float tm0 = -1e30f, tm1 = -1e30f;
#pragma unroll
        for (int g = 0; g < 8; g++) {
            tm0 = fmaxf(tm0, fmaxf(S[g][0], S[g][1]));
            tm1 = fmaxf(tm1, fmaxf(S[g][2], S[g][3]));
        }
        tm0 = fmaxf(tm0, __shfl_xor_sync(0xffffffffu, tm0, 1));
        tm0 = fmaxf(tm0, __shfl_xor_sync(0xffffffffu, tm0, 2));
        tm1 = fmaxf(tm1, __shfl_xor_sync(0xffffffffu, tm1, 1));
        tm1 = fmaxf(tm1, __shfl_xor_sync(0xffffffffu, tm1, 2));
        float mn0 = fmaxf(m0, tm0), mn1 = fmaxf(m1, tm1);
        float al0 = exp2f(m0 - mn0), al1 = exp2f(m1 - mn1);
        float s0 = 0.f, s1 = 0.f;
#pragma unroll
        for (int g = 0; g < 8; g++) {
            S[g][0] = exp2f(S[g][0] - mn0);
            S[g][1] = exp2f(S[g][1] - mn0);
            S[g][2] = exp2f(S[g][2] - mn1);
            S[g][3] = exp2f(S[g][3] - mn1);
            s0 += S[g][0] + S[g][1];
            s1 += S[g][2] + S[g][3];
        }
        s0 += __shfl_xor_sync(0xffffffffu, s0, 1);
        s0 += __shfl_xor_sync(0xffffffffu, s0, 2);
        s1 += __shfl_xor_sync(0xffffffffu, s1, 1);
        s1 += __shfl_xor_sync(0xffffffffu, s1, 2);
        l0 = l0 * al0 + s0; l1 = l1 * al1 + s1;
        m0 = mn0; m1 = mn1;
#pragma unroll
        for (int g = 0; g < 8; g++) {
            O[g][0] *= al0; O[g][1] *= al0;
            O[g][2] *= al1; O[g][3] *= al1;
        }

        // ---- pack P to fp16 A-frags ----
        uint32_t pa[4][4];
#pragma unroll
        for (int kk = 0; kk < 4; ++kk) {
            pa[kk][0] = h2pack(S[2*kk][0],   S[2*kk][1]);
            pa[kk][1] = h2pack(S[2*kk][2],   S[2*kk][3]);
            pa[kk][2] = h2pack(S[2*kk+1][0], S[2*kk+1][1]);
            pa[kk][3] = h2pack(S[2*kk+1][2], S[2*kk+1][3]);
        }

        // ---- O += P V ----
#pragma unroll
        for (int kk = 0; kk < 4; ++kk) {
#pragma unroll
            for (int gg = 0; gg < 4; ++gg) {
                uint32_t Vb[4];
                uint32_t o = v_off + kk * 2048 + gg * 32;
                ldsm_x4t(Vb[0], Vb[1], Vb[2], Vb[3], swz(bV, o));
                mma_f16(O[2*gg],   pa[kk], Vb);
                mma_f16(O[2*gg+1], pa[kk], Vb + 2);
            }
        }
    }

    // ---- epilogue: normalize, pack fp16, write g_ath ----
    const float inv0 = 1.f / l0, inv1 = 1.f / l1;
    const int r = lane >> 2;
    const int row0 = q0 + 16*wid + r;
#pragma unroll
    for (int g = 0; g < 8; g++) {
        const int dp = h * 32 + 4*g + (lane & 3);   // pair index within row
        size_t o0 = (size_t)(b*NT + row0) * 512 + dp;
        g_ath[o0] = h2pack(O[g][0] * inv0, O[g][1] * inv0);
        size_t o1 = (size_t)(b*NT + row0 + 8) * 512 + dp;
        g_ath[o1] = h2pack(O[g][2] * inv1, O[g][3] * inv1);
    }
}

// ---------------------------------------------------------------------------
// Launch
// ---------------------------------------------------------------------------
extern "C" void kernel_launch(void* const* d_in, const int* in_sizes, int n_in,
                              void* d_out, int out_size) {
    const float* x    = (const float*)d_in[0];
    const float* pk   = (const float*)d_in[1];
    const float* pv   = (const float*)d_in[2];
    const float* Wqkv = (const float*)d_in[3];
    const float* bqkv = (const float*)d_in[4];
    const float* Wout = (const float*)d_in[5];
    const float* bout = (const float*)d_in[6];
    float* out = (float*)d_out;

    cudaFuncSetAttribute(attn_kernel,
                         cudaFuncAttributeMaxDynamicSharedMemorySize, ATTN_SMEM);
    cudaFuncSetAttribute(mma_gemm_kernel<0>,
                         cudaFuncAttributeMaxDynamicSharedMemorySize, GEMM_SMEM);
    cudaFuncSetAttribute(mma_gemm_kernel<1>,
                         cudaFuncAttributeMaxDynamicSharedMemorySize, GEMM_SMEM);

    __half *wq, *wo;
    uint32_t *xh, *ath;
    cudaGetSymbolAddress((void**)&wq,  g_wqkv);
    cudaGetSymbolAddress((void**)&wo,  g_wout);
    cudaGetSymbolAddress((void**)&xh,  g_xh);
    cudaGetSymbolAddress((void**)&ath, g_ath);

    prep_kernel<<<PREP_BLOCKS, 256>>>(x, Wqkv);
    mma_gemm_kernel<0><<<2048, 256, GEMM_SMEM>>>(xh, wq, bqkv, nullptr, Wout, pk, pv);
    attn_kernel<<<dim3(16, 32), 256, ATTN_SMEM>>>();
    mma_gemm_kernel<1><<<dim3(8, 32), 256, GEMM_SMEM>>>(ath, wo, bout, out,
                                                        nullptr, nullptr, nullptr);
}

// round 17
// speedup vs baseline: 2.1203x; 1.0080x over previous
#include <cuda_runtime.h>
#include <cuda_bf16.h>
#include <cuda_fp16.h>
#include <cstdint>

// Problem constants
#define NB 2
#define NT 2048
#define NC 1024
#define NH 16
#define ND 64
#define NP 16
#define NS 2064      // NP + NT
#define SPAD 2112    // 33 chunks of 64
#define NROWS 4096   // NB * NT

// q pre-scale: 0.125 * log2(e), so scores come out of QK in log2 domain
#define QSCALE 0.18033688011112042f

// ---------------------------------------------------------------------------
// Scratch (allocation-free: __device__ globals). Packed-pair u32 arrays.
// ---------------------------------------------------------------------------
__device__ uint32_t g_xh[(size_t)NROWS*NC/2];        // x fp16 pairs [row][512]
__device__ uint32_t g_ath[(size_t)NROWS*NC/2];       // attention out fp16 pairs
__device__ uint32_t g_qh[NB*NH*NT*ND/2];             // q fp16 (xQSCALE)
__device__ uint32_t g_kh[NB*NH*SPAD*ND/2];           // k fp16
__device__ uint32_t g_vh[NB*NH*SPAD*ND/2];           // v fp16
// Pre-transposed fp16 weights, [N][K=1024]
__device__ __half g_wqkv[3*NC*NC];
__device__ __half g_wout[NC*NC];
// per-(b,qtile) completion counters for attn -> gemm1 flag sync (32 tiles)
__device__ int g_qdone[32];

// ---------------------------------------------------------------------------
// Helpers (family-agnostic: ldmatrix / mma.sync / cp.async only)
// ---------------------------------------------------------------------------
__device__ __forceinline__ uint32_t smem_u32(const void* p) {
    uint32_t a;
    asm("{ .reg .u64 t; cvta.to.shared.u64 t, %1; cvt.u32.u64 %0, t; }" : "=r"(a) : "l"(p));
    return a;
}

#define CP_ASYNC16(dst, src) \
    asm volatile("cp.async.cg.shared.global [%0], [%1], 16;" :: "r"(dst), "l"(src) : "memory")
#define CP_COMMIT() asm volatile("cp.async.commit_group;" ::: "memory")
#define CP_WAIT0()  asm volatile("cp.async.wait_group 0;" ::: "memory")
#define CP_WAIT1()  asm volatile("cp.async.wait_group 1;" ::: "memory")

#define SW128(o) ((o) ^ (((o) >> 3) & 0x70))
__device__ __forceinline__ uint32_t swz(uint32_t base, uint32_t off) {
    return base + SW128(off);
}

__device__ __forceinline__ void ldsm_x4(uint32_t& r0, uint32_t& r1, uint32_t& r2, uint32_t& r3,
                                        uint32_t addr) {
    asm volatile("ldmatrix.sync.aligned.m8n8.x4.shared.b16 {%0,%1,%2,%3}, [%4];"
                 : "=r"(r0), "=r"(r1), "=r"(r2), "=r"(r3) : "r"(addr));
}
__device__ __forceinline__ void ldsm_x4t(uint32_t& r0, uint32_t& r1, uint32_t& r2, uint32_t& r3,
                                         uint32_t addr) {
    asm volatile("ldmatrix.sync.aligned.m8n8.x4.trans.shared.b16 {%0,%1,%2,%3}, [%4];"
                 : "=r"(r0), "=r"(r1), "=r"(r2), "=r"(r3) : "r"(addr));
}

__device__ __forceinline__ void mma_f16(float* d, const uint32_t* a, const uint32_t* b) {
    asm volatile("mma.sync.aligned.m16n8k16.row.col.f32.f16.f16.f32 "
                 "{%0,%1,%2,%3}, {%4,%5,%6,%7}, {%8,%9}, {%0,%1,%2,%3};"
                 : "+f"(d[0]), "+f"(d[1]), "+f"(d[2]), "+f"(d[3])
                 : "r"(a[0]), "r"(a[1]), "r"(a[2]), "r"(a[3]), "r"(b[0]), "r"(b[1]));
}

__device__ __forceinline__ uint32_t h2pack(float a, float b) {
    __half2 h = __floats2half2_rn(a, b);
    return *reinterpret_cast<uint32_t*>(&h);
}

// ---------------------------------------------------------------------------
// Prep launch: Wqkv transpose tiles [0,3072) + xprep float4 [3072,7168).
// Block 0 also zeroes the attn->gemm1 counters (fresh every graph replay).
// ---------------------------------------------------------------------------
#define PREP_WQ   3072
#define PREP_XP   4096
#define PREP_BLOCKS (PREP_WQ + PREP_XP)

__global__ __launch_bounds__(256) void prep_kernel(
        const float* __restrict__ x,
        const float* __restrict__ Wqkv) {
    const int blk = blockIdx.x;
    const int tid = threadIdx.x;

    if (blk == 0 && tid < 32) g_qdone[tid] = 0;

    if (blk < PREP_WQ) {
        __shared__ float tile[32][33];
        const int N = 3*NC;
        const int ntx = N >> 5;
        const int n0 = (blk % ntx) * 32, k0 = (blk / ntx) * 32;
        const int tx = tid & 31, ty = tid >> 5;
#pragma unroll
        for (int i = 0; i < 32; i += 8)
            tile[ty + i][tx] = Wqkv[(size_t)(k0 + ty + i) * N + n0 + tx];
        __syncthreads();
#pragma unroll
        for (int i = 0; i < 32; i += 8)
            g_wqkv[(size_t)(n0 + ty + i) * NC + k0 + tx] = __float2half_rn(tile[tx][ty + i]);
    } else {
        // xprep: 2 pairs (float4) per thread
        int idx = (blk - PREP_WQ) * 256 + tid;      // float4 index
        float4 v = *(const float4*)(x + 4 * (size_t)idx);
        g_xh[2*idx]     = h2pack(v.x, v.y);
        g_xh[2*idx + 1] = h2pack(v.z, v.w);
    }
}

// ---------------------------------------------------------------------------
// GEMM core (single-pass fp16, 3-stage pipeline) shared by gemm0 and fused
// gemm1. 256 threads = 8 warps (4m x 2n), CTA tile 128x128, K chunks of 64.
// ---------------------------------------------------------------------------
#define GEMM_SMEM (3*32768 + 1024)
#define NCH 16
#define G0_TILES 768
#define G0_WO    1024

template<int MODE>
__device__ __forceinline__ void gemm_body(
        int bx, int by, char* dsm,
        const uint32_t* __restrict__ A_g,
        const __half* __restrict__ W,
        const float* __restrict__ bias,
        float* __restrict__ out) {
    const int tid = threadIdx.x;
    const uint32_t sb = (smem_u32(dsm) + 1023u) & ~1023u;
    const int lane = tid & 31;
    const int wm = (tid >> 5) & 3;          // warp m (0..3), rows 32*wm
    const int wn = tid >> 7;                // warp n (0..1), cols 64*wn
    const int r0 = by * 128;
    const int c0 = bx * 128;

    const uint32_t a_off = (uint32_t)((32*wm + (lane & 15)) * 128 + (lane >> 4) * 16);
    const uint32_t b_off = (uint32_t)((64*wn + ((lane >> 4) & 1) * 8 + (lane & 7)) * 128
                                      + ((lane >> 3) & 1) * 16);
    const int ldrow = tid >> 3;             // 0..31
    const int ldc8  = (tid & 7) * 8;        // fp16-element col offset

    float acc[2][8][4];
#pragma unroll
    for (int mf = 0; mf < 2; mf++)
#pragma unroll
        for (int ng = 0; ng < 8; ng++)
#pragma unroll
            for (int c = 0; c < 4; c++) acc[mf][ng][c] = 0.f;

    auto loadStage = [&](int ch, uint32_t bb) {
#pragma unroll
        for (int it = 0; it < 4; ++it) {
            int row = ldrow + it * 32;
            uint32_t off = SW128((uint32_t)(row * 128 + ldc8 * 2));
            size_t ga = (size_t)(r0 + row) * (NC/2) + (ch * 64 + ldc8) / 2;
            CP_ASYNC16(bb + off, A_g + ga);
            size_t gb = (size_t)(c0 + row) * NC + ch * 64 + ldc8;
            CP_ASYNC16(bb + 16384u + off, W + gb);
        }
    };

    loadStage(0, sb);
    CP_COMMIT();
    loadStage(1, sb + 32768u);
    CP_COMMIT();

    for (int ch = 0; ch < NCH; ++ch) {
        if (ch == NCH - 1) { CP_WAIT0(); } else { CP_WAIT1(); }
        __syncthreads();    // chunk ch visible to all; all warps done with ch-1
        if (ch + 2 < NCH) {
            loadStage(ch + 2, sb + (uint32_t)((ch + 2) % 3) * 32768u);
            CP_COMMIT();
        }

        const uint32_t base = sb + (uint32_t)(ch % 3) * 32768u;
        const uint32_t bA = base, bB = base + 16384u;
#pragma unroll
        for (int kk = 0; kk < 4; ++kk) {
            uint32_t Af[2][4];
#pragma unroll
            for (int mf = 0; mf < 2; mf++) {
                uint32_t o = a_off + kk * 32 + mf * 2048;
                ldsm_x4(Af[mf][0], Af[mf][1], Af[mf][2], Af[mf][3], swz(bA, o));
            }
            uint32_t Bf[4][4];
#pragma unroll
            for (int g = 0; g < 4; ++g) {
                uint32_t o = b_off + g * 2048 + kk * 32;
                ldsm_x4(Bf[g][0], Bf[g][1], Bf[g][2], Bf[g][3], swz(bB, o));
            }
#pragma unroll
            for (int g = 0; g < 4; ++g)
#pragma unroll
                for (int mf = 0; mf < 2; mf++) {
                    mma_f16(acc[mf][2*g],   Af[mf], Bf[g]);
                    mma_f16(acc[mf][2*g+1], Af[mf], Bf[g] + 2);
                }
        }
    }

    // ---- epilogue ----
    const int g4 = lane >> 2, t4 = lane & 3;
    const int colb = c0 + 64 * wn;
    const int which = colb >> 10;               // MODE 0 only
    const int hh = (colb >> 6) & (NH - 1);
#pragma unroll
    for (int ng = 0; ng < 8; ++ng) {
        const int col = colb + 8 * ng + 2 * t4;
        const float b0v = bias[col], b1v = bias[col + 1];
#pragma unroll
        for (int mf = 0; mf < 2; mf++) {
            const int row = r0 + 32 * wm + 16 * mf + g4;
            const float* ac = acc[mf][ng];
            if (MODE == 1) {
                float2 v0 = make_float2(ac[0] + b0v, ac[1] + b1v);
                float2 v1 = make_float2(ac[2] + b0v, ac[3] + b1v);
                *(float2*)&out[(size_t)row * NC + col] = v0;
                *(float2*)&out[(size_t)(row + 8) * NC + col] = v1;
            } else {
                const int dp = (col & (ND - 1)) >> 1;
#pragma unroll
                for (int rr = 0; rr < 2; rr++) {
                    const int r = row + 8*rr;
                    const int b = r >> 11, t = r & (NT - 1);
                    const int bh = b * NH + hh;
                    float x = ac[2*rr] + b0v, y = ac[2*rr+1] + b1v;
                    if (which == 0) {
                        size_t o = ((size_t)bh * NT + t) * 32 + dp;
                        g_qh[o] = h2pack(x * QSCALE, y * QSCALE);
                    } else if (which == 1) {
                        size_t o = ((size_t)bh * SPAD + NP + t) * 32 + dp;
                        g_kh[o] = h2pack(x, y);
                    } else {
                        size_t o = ((size_t)bh * SPAD + NP + t) * 32 + dp;
                        g_vh[o] = h2pack(x, y);
                    }
                }
            }
        }
    }
}

// ---------------------------------------------------------------------------
// gemm0 launch: [0,768) GEMM tiles, [768,1792) Wout transpose (tail fill),
// [1792,2048) prefix fill + K/V pad rows (tail fill).
// ---------------------------------------------------------------------------
__global__ __launch_bounds__(256, 2) void gemm0_kernel(
        const uint32_t* __restrict__ A_g,
        const __half* __restrict__ W,
        const float* __restrict__ bias,
        const float* __restrict__ Wout,
        const float* __restrict__ pk,
        const float* __restrict__ pv) {
    extern __shared__ char dsm[];
    const int tid = threadIdx.x;
    const int bid = blockIdx.x;

    if (bid >= G0_TILES) {
        if (bid < G0_TILES + G0_WO) {
            // ---- Wout transpose + fp16 (tail fill) ----
            float (*tile)[33] = reinterpret_cast<float(*)[33]>(dsm);
            const int tb = bid - G0_TILES;
            const int n0 = (tb & 31) * 32, k0 = (tb >> 5) * 32;
            const int tx = tid & 31, ty = tid >> 5;
#pragma unroll
            for (int i = 0; i < 32; i += 8)
                tile[ty + i][tx] = Wout[(size_t)(k0 + ty + i) * NC + n0 + tx];
            __syncthreads();
#pragma unroll
            for (int i = 0; i < 32; i += 8)
                g_wout[(size_t)(n0 + ty + i) * NC + k0 + tx] =
                    __float2half_rn(tile[tx][ty + i]);
        } else {
            // ---- prefix fill + K/V pad rows (tail fill) ----
            int idx = (bid - G0_TILES - G0_WO) * 256 + tid;
            if (idx < NH*NP*32) {
                int h = idx >> 9;
                int p = (idx >> 5) & (NP - 1);
                int dp = idx & 31;
                const float* kp = pk + ((size_t)h * NP + p) * ND + 2*dp;
                const float* vp = pv + ((size_t)h * NP + p) * ND + 2*dp;
                uint32_t kh = h2pack(kp[0], kp[1]);
                uint32_t vh = h2pack(vp[0], vp[1]);
#pragma unroll
                for (int b = 0; b < NB; b++) {
                    size_t o = ((size_t)(b*NH + h) * SPAD + p) * 32 + dp;
                    g_kh[o] = kh; g_vh[o] = vh;
                }
            } else {
                int j = idx - NH*NP*32;
                if (j < NB*NH*48*32) {
                    int bh = j / (48*32);
                    int rem = j % (48*32);
                    int r = NS + (rem >> 5);
                    int dp = rem & 31;
                    size_t o = ((size_t)bh * SPAD + r) * 32 + dp;
                    g_kh[o] = 0; g_vh[o] = 0;
                }
            }
        }
        return;
    }
    gemm_body<0>(bid % 24, bid / 24, dsm, A_g, W, bias, nullptr);
}

// ---------------------------------------------------------------------------
// Fused attention + gemm1 launch (768 blocks):
//   [0,512)   attention: (qtile = bid&15, bh = bid>>4); signals qdone.
//   [512,768) gemm1 tiles: spin on qdone[row-block]==16, then GEMM -> d_out.
// Deadlock-free: 256 spinners < 296 resident capacity => attention always
// has slots to progress.
// ---------------------------------------------------------------------------
#define NCHUNK 33
#define FUSED_ATTN 512

__global__ __launch_bounds__(256, 2) void attn_gemm1_kernel(
        const __half* __restrict__ Wo,
        const float* __restrict__ bout,
        float* __restrict__ out) {
    extern __shared__ char dsm[];
    const int bid = blockIdx.x;
    const int tid = threadIdx.x;

    if (bid >= FUSED_ATTN) {
        // ================= gemm1 tile =================
        const int tb = bid - FUSED_ATTN;
        const int bx = tb & 7, by = tb >> 3;     // by = row block = b*16 + qtile
        if (tid == 0) {
            while (((volatile int*)g_qdone)[by] < NH) __nanosleep(200);
        }
        __syncthreads();
        __threadfence();
        uint32_t* ath;
        asm("cvta.global.u64 %0, g_ath;" : "=l"(ath));
        gemm_body<1>(bx, by, dsm, (const uint32_t*)ath, Wo, bout, out);
        return;
    }

    // ================= attention =================
    const uint32_t sb  = (smem_u32(dsm) + 1023u) & ~1023u;
    const uint32_t sQ = sb;
    const uint32_t sBuf0 = sb + 16384u;       // 3 bufs, each: K 8K | V 8K

    const int qt = bid & 15;
    const int bh = bid >> 4;
    const int q0 = qt * 128;
    const int b = bh >> 4, h = bh & (NH - 1);
    const int lane = tid & 31;
    const int wid = tid >> 5;

    const uint32_t* Qp  = g_qh + ((size_t)bh * NT + q0) * 32;
    const uint32_t* Khp = g_kh + (size_t)bh * SPAD * 32;
    const uint32_t* Vhp = g_vh + (size_t)bh * SPAD * 32;

    const uint32_t a_off = (uint32_t)((16*wid + (lane & 15)) * 128 + (lane >> 4) * 16);
    const uint32_t b_off = (uint32_t)((((lane >> 4) & 1) * 8 + (lane & 7)) * 128
                                      + ((lane >> 3) & 1) * 16);
    const uint32_t v_off = (uint32_t)((lane & 15) * 128 + (lane >> 4) * 16);

    auto loadChunk = [&](int ci, uint32_t bb) {
#pragma unroll
        for (int it = 0; it < 4; ++it) {
            int idx = tid + it * 256;           // 0..1023
            int ten = idx >> 9;                 // 0 K, 1 V
            int r = (idx & 511) >> 3;
            int seg = idx & 7;
            const uint32_t* base = ten ? Vhp : Khp;
            const uint32_t* src = base + (size_t)(ci * 64 + r) * 32 + seg * 4;
            uint32_t dst = bb + (uint32_t)ten * 8192u + SW128((uint32_t)(r * 128 + seg * 16));
            CP_ASYNC16(dst, src);
        }
    };

    // Q load folded into group 0
#pragma unroll
    for (int it = 0; it < 4; ++it) {
        int idx = tid + it * 256;
        int r = idx >> 3;
        int seg = idx & 7;
        const uint32_t* src = Qp + (size_t)r * 32 + seg * 4;
        uint32_t dst = sQ + SW128((uint32_t)(r * 128 + seg * 16));
        CP_ASYNC16(dst, src);
    }
    loadChunk(0, sBuf0);
    CP_COMMIT();
    loadChunk(1, sBuf0 + 16384u);
    CP_COMMIT();

    float O[8][4];
#pragma unroll
    for (int g = 0; g < 8; g++)
#pragma unroll
        for (int c = 0; c < 4; c++) O[g][c] = 0.f;
    float m0 = -1e30f, m1 = -1e30f, l0 = 0.f, l1 = 0.f;

    for (int ci = 0; ci < NCHUNK; ++ci) {
        if (ci == NCHUNK - 1) { CP_WAIT0(); } else { CP_WAIT1(); }
        __syncthreads();    // chunk ci (and Q) visible; all warps done with ci-1
        if (ci + 2 < NCHUNK) {
            loadChunk(ci + 2, sBuf0 + (uint32_t)((ci + 2) % 3) * 16384u);
            CP_COMMIT();
        }

        const uint32_t buf = sBuf0 + (uint32_t)(ci % 3) * 16384u;
        const uint32_t bK = buf, bV = buf + 8192u;

        // ---- S = Q K^T (single-pass fp16, scores in log2 domain) ----
        float S[8][4];
#pragma unroll
        for (int g = 0; g < 8; g++)
#pragma unroll
            for (int c = 0; c < 4; c++) S[g][c] = 0.f;
#pragma unroll
        for (int kk = 0; kk < 4; ++kk) {
            uint32_t Af[4];
            ldsm_x4(Af[0], Af[1], Af[2], Af[3], swz(sQ, a_off + kk * 32));
#pragma unroll
            for (int gp = 0; gp < 2; ++gp) {
                uint32_t K0[4], K1[4];
                uint32_t o0 = b_off + (2*gp) * 2048 + kk * 32;
                uint32_t o1 = b_off + (2*gp+1) * 2048 + kk * 32;
                ldsm_x4(K0[0], K0[1], K0[2], K0[3], swz(bK, o0));
                ldsm_x4(K1[0], K1[1], K1[2], K1[3], swz(bK, o1));
                mma_f16(S[4*gp],   Af, K0); mma_f16(S[4*gp+1], Af, K0 + 2);
                mma_f16(S[4*gp+2], Af, K1); mma_f16(S[4*gp+3], Af, K1 + 2);
            }
        }

        // ---- tail mask (chunk 32: only cols 0..15 valid => frags g>=2) ----
        if (ci == NCHUNK - 1) {
#pragma unroll
            for (int g = 2; g < 8; g++)
#pragma unroll
                for (int c = 0; c < 4; c++) S[g][c] = -1e30f;
        }

        // ---- online softmax (exp2 domain) ----
        float tm0 = -1e30f, tm1 = -1e30f;
#pragma unroll
        for (int g = 0; g < 8; g++) {
            tm0 = fmaxf(tm0, fmaxf(S[g][0], S[g][1]));
            tm1 = fmaxf(tm1, fmaxf(S[g][2], S[g][3]));
        }
        tm0 = fmaxf(tm0, __shfl_xor_sync(0xffffffffu, tm0, 1));
        tm0 = fmaxf(tm0, __shfl_xor_sync(0xffffffffu, tm0, 2));
        tm1 = fmaxf(tm1, __shfl_xor_sync(0xffffffffu, tm1, 1));
        tm1 = fmaxf(tm1, __shfl_xor_sync(0xffffffffu, tm1, 2));
        float mn0 = fmaxf(m0, tm0), mn1 = fmaxf(m1, tm1);
        float al0 = exp2f(m0 - mn0), al1 = exp2f(m1 - mn1);
        float s0 = 0.f, s1 = 0.f;
#pragma unroll
        for (int g = 0; g < 8; g++) {
            S[g][0] = exp2f(S[g][0] - mn0);
            S[g][1] = exp2f(S[g][1] - mn0);
            S[g][2] = exp2f(S[g][2] - mn1);
            S[g][3] = exp2f(S[g][3] - mn1);
            s0 += S[g][0] + S[g][1];
            s1 += S[g][2] + S[g][3];
        }
        s0 += __shfl_xor_sync(0xffffffffu, s0, 1);
        s0 += __shfl_xor_sync(0xffffffffu, s0, 2);
        s1 += __shfl_xor_sync(0xffffffffu, s1, 1);
        s1 += __shfl_xor_sync(0xffffffffu, s1, 2);
        l0 = l0 * al0 + s0; l1 = l1 * al1 + s1;
        m0 = mn0; m1 = mn1;
#pragma unroll
        for (int g = 0; g < 8; g++) {
            O[g][0] *= al0; O[g][1] *= al0;
            O[g][2] *= al1; O[g][3] *= al1;
        }

        // ---- pack P to fp16 A-frags ----
        uint32_t pa[4][4];
#pragma unroll
        for (int kk = 0; kk < 4; ++kk) {
            pa[kk][0] = h2pack(S[2*kk][0],   S[2*kk][1]);
            pa[kk][1] = h2pack(S[2*kk][2],   S[2*kk][3]);
            pa[kk][2] = h2pack(S[2*kk+1][0], S[2*kk+1][1]);
            pa[kk][3] = h2pack(S[2*kk+1][2], S[2*kk+1][3]);
        }

        // ---- O += P V ----
#pragma unroll
        for (int kk = 0; kk < 4; ++kk) {
#pragma unroll
            for (int gg = 0; gg < 4; ++gg) {
                uint32_t Vb[4];
                uint32_t o = v_off + kk * 2048 + gg * 32;
                ldsm_x4t(Vb[0], Vb[1], Vb[2], Vb[3], swz(bV, o));
                mma_f16(O[2*gg],   pa[kk], Vb);
                mma_f16(O[2*gg+1], pa[kk], Vb + 2);
            }
        }
    }

    // ---- epilogue: normalize, pack fp16, write g_ath ----
    const float inv0 = 1.f / l0, inv1 = 1.f / l1;
    const int r = lane >> 2;
    const int row0 = q0 + 16*wid + r;
#pragma unroll
    for (int g = 0; g < 8; g++) {
        const int dp = h * 32 + 4*g + (lane & 3);   // pair index within row
        size_t o0 = (size_t)(b*NT + row0) * 512 + dp;
        g_ath[o0] = h2pack(O[g][0] * inv0, O[g][1] * inv0);
        size_t o1 = (size_t)(b*NT + row0 + 8) * 512 + dp;
        g_ath[o1] = h2pack(O[g][2] * inv1, O[g][3] * inv1);
    }

    // ---- signal completion of this (b, qtile, h) ----
    __syncthreads();
    if (tid == 0) {
        __threadfence();
        atomicAdd(&g_qdone[b * 16 + qt], 1);
    }
}

// ---------------------------------------------------------------------------
// Launch
// ---------------------------------------------------------------------------
extern "C" void kernel_launch(void* const* d_in, const int* in_sizes, int n_in,
                              void* d_out, int out_size) {
    const float* x    = (const float*)d_in[0];
    const float* pk   = (const float*)d_in[1];
    const float* pv   = (const float*)d_in[2];
    const float* Wqkv = (const float*)d_in[3];
    const float* bqkv = (const float*)d_in[4];
    const float* Wout = (const float*)d_in[5];
    const float* bout = (const float*)d_in[6];
    float* out = (float*)d_out;

    cudaFuncSetAttribute(gemm0_kernel,
                         cudaFuncAttributeMaxDynamicSharedMemorySize, GEMM_SMEM);
    cudaFuncSetAttribute(attn_gemm1_kernel,
                         cudaFuncAttributeMaxDynamicSharedMemorySize, GEMM_SMEM);

    __half *wq, *wo;
    uint32_t *xh;
    cudaGetSymbolAddress((void**)&wq,  g_wqkv);
    cudaGetSymbolAddress((void**)&wo,  g_wout);
    cudaGetSymbolAddress((void**)&xh,  g_xh);

    prep_kernel<<<PREP_BLOCKS, 256>>>(x, Wqkv);
    gemm0_kernel<<<2048, 256, GEMM_SMEM>>>(xh, wq, bqkv, Wout, pk, pv);
    attn_gemm1_kernel<<<768, 256, GEMM_SMEM>>>(wo, bout, out);
}